// round 1
// baseline (speedup 1.0000x reference)
#include <cuda_runtime.h>
#include <cstdint>

#define NSEQ 2048
#define DDIM 1024
#define BATCH 8
#define TWO_N (2*NSEQ)

// ---------------- scratch (static device globals: allocation-free) ----------
__device__ float g_q[(size_t)BATCH*NSEQ*DDIM];   // 64 MB
__device__ float g_k[(size_t)BATCH*NSEQ*DDIM];   // 64 MB
__device__ float g_v[(size_t)BATCH*NSEQ*DDIM];   // 64 MB
__device__ float g_s[(size_t)BATCH*NSEQ*NSEQ];   // 134 MB (scores -> attn in place)
__device__ float g_c[TWO_N];                     // circulant first column

// ---------------- packed f32x2 helpers (FFMA2: 2x fp32 pipe rate) ----------
__device__ __forceinline__ void fma2(unsigned long long &d,
                                     unsigned long long a,
                                     unsigned long long b) {
    asm("fma.rn.f32x2 %0, %1, %2, %0;" : "+l"(d) : "l"(a), "l"(b));
}
__device__ __forceinline__ unsigned long long dup2(float a) {
    unsigned long long r;
    unsigned ai = __float_as_uint(a);
    asm("mov.b64 %0, {%1, %1};" : "=l"(r) : "r"(ai));
    return r;
}
__device__ __forceinline__ float2 unpack2(unsigned long long d) {
    unsigned lo, hi;
    asm("mov.b64 {%0, %1}, %2;" : "=r"(lo), "=r"(hi) : "l"(d));
    return make_float2(__uint_as_float(lo), __uint_as_float(hi));
}

// ---------------- shared GEMM mainloop: 128x128 tile, BK=8, 256 thr --------
// C tile = A[rowTile:+128, :K] * op(B), op(B)=B (KxN row-major) or B^T (NxK).
// Accumulators: 8x4 packed f32x2 (8 rows x 8 cols per thread).
template<bool TRANSB>
__device__ __forceinline__ void gemm_main(
    const float* __restrict__ A, const float* __restrict__ B,
    int lda, int ldb, int K, int rowTile, int colTile,
    float* As, float* Bs, unsigned long long acc[8][4])
{
    const int tid = threadIdx.x;
    const int tr = tid >> 4;      // 0..15 -> row group
    const int tc = tid & 15;      // 0..15 -> col group

#pragma unroll
    for (int m = 0; m < 8; m++)
#pragma unroll
        for (int p = 0; p < 4; p++) acc[m][p] = 0ull;

    const int arow  = tid >> 1;   // 0..127
    const int aquad = tid & 1;    // 0..1 (which float4 of the 8-wide k slice)

    for (int k0 = 0; k0 < K; k0 += 8) {
        // --- A tile [128 x 8] -> As[k][m] (transposed in smem, stride 132) ---
        {
            float4 a4 = *(const float4*)(A + (size_t)(rowTile + arow) * lda + k0 + aquad * 4);
            As[(aquad * 4 + 0) * 132 + arow] = a4.x;
            As[(aquad * 4 + 1) * 132 + arow] = a4.y;
            As[(aquad * 4 + 2) * 132 + arow] = a4.z;
            As[(aquad * 4 + 3) * 132 + arow] = a4.w;
        }
        // --- B tile -> Bs[k][n] ---
        if (TRANSB) {
            // B is [N x K] row-major; tile rows are n, contiguous in k.
            float4 b4 = *(const float4*)(B + (size_t)(colTile + arow) * ldb + k0 + aquad * 4);
            Bs[(aquad * 4 + 0) * 132 + arow] = b4.x;
            Bs[(aquad * 4 + 1) * 132 + arow] = b4.y;
            Bs[(aquad * 4 + 2) * 132 + arow] = b4.z;
            Bs[(aquad * 4 + 3) * 132 + arow] = b4.w;
        } else {
            int krow  = tid >> 5;          // 0..7
            int lane4 = (tid & 31) * 4;    // 0..124
            float4 b4 = *(const float4*)(B + (size_t)(k0 + krow) * ldb + colTile + lane4);
            *(float4*)&Bs[krow * 132 + lane4] = b4;
        }
        __syncthreads();

#pragma unroll
        for (int kk = 0; kk < 8; kk++) {
            const float4* ap = (const float4*)&As[kk * 132 + tr * 8];
            float4 av0 = ap[0], av1 = ap[1];
            unsigned long long aa[8];
            aa[0] = dup2(av0.x); aa[1] = dup2(av0.y);
            aa[2] = dup2(av0.z); aa[3] = dup2(av0.w);
            aa[4] = dup2(av1.x); aa[5] = dup2(av1.y);
            aa[6] = dup2(av1.z); aa[7] = dup2(av1.w);

            const ulonglong2* bp = (const ulonglong2*)&Bs[kk * 132 + tc * 8];
            ulonglong2 b01 = bp[0], b23 = bp[1];
            unsigned long long bb[4] = { b01.x, b01.y, b23.x, b23.y };

#pragma unroll
            for (int m = 0; m < 8; m++)
#pragma unroll
                for (int p = 0; p < 4; p++)
                    fma2(acc[m][p], aa[m], bb[p]);
        }
        __syncthreads();
    }
}

// ---------------- kernel 1: circulant bias column c = real(ifft(R)) --------
__global__ void bias_kernel(const float* __restrict__ R) {
    int t = blockIdx.x * blockDim.x + threadIdx.x;   // 0..4095
    if (t >= TWO_N) return;
    const float w = 6.283185307179586f / (float)TWO_N;
    float s = 0.f;
    for (int j = 0; j < TWO_N; j++) {
        int r = (j * t) & (TWO_N - 1);
        s += R[j] * cosf(w * (float)r);
    }
    g_c[t] = s * (1.0f / (float)TWO_N);
}

// ---------------- kernel 2: QKV projections (z selects which) --------------
__global__ __launch_bounds__(256) void proj_kernel(
    const float* __restrict__ x,
    const float* __restrict__ Wq, const float* __restrict__ Wk, const float* __restrict__ Wv,
    const float* __restrict__ tq, const float* __restrict__ tk, const float* __restrict__ tv)
{
    __shared__ float As[8 * 132];
    __shared__ float Bs[8 * 132];
    int which = blockIdx.z;
    const float* W = (which == 0) ? Wq : (which == 1) ? Wk : Wv;
    float tau      = (which == 0) ? *tq : (which == 1) ? *tk : *tv;
    float* out     = (which == 0) ? g_q : (which == 1) ? g_k : g_v;

    int rowTile = blockIdx.y * 128;
    int colTile = blockIdx.x * 128;
    unsigned long long acc[8][4];
    gemm_main<false>(x, W, DDIM, DDIM, DDIM, rowTile, colTile, As, Bs, acc);

    int tr = threadIdx.x >> 4, tc = threadIdx.x & 15;
    int r0 = rowTile + tr * 8, c0 = colTile + tc * 8;
#pragma unroll
    for (int m = 0; m < 8; m++)
#pragma unroll
        for (int p = 0; p < 4; p++) {
            float2 v = unpack2(acc[m][p]);
            v.x *= tau; v.y *= tau;
            *(float2*)&out[(size_t)(r0 + m) * DDIM + c0 + 2 * p] = v;
        }
}

// ---------------- kernel 3: E = scale*(q k^T) + P + circ bias --------------
__global__ __launch_bounds__(256) void scores_kernel(const float* __restrict__ P) {
    __shared__ float As[8 * 132];
    __shared__ float Bs[8 * 132];
    int b = blockIdx.z;
    const float* q = g_q + (size_t)b * NSEQ * DDIM;
    const float* k = g_k + (size_t)b * NSEQ * DDIM;
    float* S       = g_s + (size_t)b * NSEQ * NSEQ;

    int rowTile = blockIdx.y * 128;
    int colTile = blockIdx.x * 128;
    unsigned long long acc[8][4];
    gemm_main<true>(q, k, DDIM, DDIM, DDIM, rowTile, colTile, As, Bs, acc);

    const float scale = 0.03125f;  // sqrt(1/1024)
    int tr = threadIdx.x >> 4, tc = threadIdx.x & 15;
    int r0 = rowTile + tr * 8, c0 = colTile + tc * 8;
#pragma unroll
    for (int m = 0; m < 8; m++) {
        int i = r0 + m;
#pragma unroll
        for (int p = 0; p < 4; p++) {
            int j = c0 + 2 * p;
            float2 v = unpack2(acc[m][p]);
            v.x = v.x * scale + P[(size_t)i * NSEQ + j]     + g_c[(i - j) & (TWO_N - 1)];
            v.y = v.y * scale + P[(size_t)i * NSEQ + j + 1] + g_c[(i - j - 1) & (TWO_N - 1)];
            *(float2*)&S[(size_t)i * NSEQ + j] = v;
        }
    }
}

// ---------------- kernel 4: row softmax over 2048 (one block per row) ------
__global__ __launch_bounds__(256) void softmax_kernel() {
    size_t row = blockIdx.x;
    float* p = g_s + row * NSEQ;
    int t = threadIdx.x;
    int lane = t & 31, wid = t >> 5;
    __shared__ float red[8];

    float x[8];
#pragma unroll
    for (int i = 0; i < 8; i++) x[i] = p[t + i * 256];

    float m = x[0];
#pragma unroll
    for (int i = 1; i < 8; i++) m = fmaxf(m, x[i]);
#pragma unroll
    for (int o = 16; o; o >>= 1) m = fmaxf(m, __shfl_xor_sync(0xFFFFFFFFu, m, o));
    if (lane == 0) red[wid] = m;
    __syncthreads();
    float bm = red[0];
#pragma unroll
    for (int i = 1; i < 8; i++) bm = fmaxf(bm, red[i]);
    __syncthreads();

    float s = 0.f;
#pragma unroll
    for (int i = 0; i < 8; i++) { x[i] = expf(x[i] - bm); s += x[i]; }
#pragma unroll
    for (int o = 16; o; o >>= 1) s += __shfl_xor_sync(0xFFFFFFFFu, s, o);
    if (lane == 0) red[wid] = s;
    __syncthreads();
    float tot = red[0];
#pragma unroll
    for (int i = 1; i < 8; i++) tot += red[i];
    float inv = 1.0f / tot;

#pragma unroll
    for (int i = 0; i < 8; i++) p[t + i * 256] = x[i] * inv;
}

// ---------------- kernel 5: out = A @ v ------------------------------------
__global__ __launch_bounds__(256) void out_kernel(float* __restrict__ out) {
    __shared__ float As[8 * 132];
    __shared__ float Bs[8 * 132];
    int b = blockIdx.z;
    const float* Amat = g_s + (size_t)b * NSEQ * NSEQ;
    const float* V    = g_v + (size_t)b * NSEQ * DDIM;
    float* O          = out + (size_t)b * NSEQ * DDIM;

    int rowTile = blockIdx.y * 128;
    int colTile = blockIdx.x * 128;
    unsigned long long acc[8][4];
    gemm_main<false>(Amat, V, NSEQ, DDIM, NSEQ, rowTile, colTile, As, Bs, acc);

    int tr = threadIdx.x >> 4, tc = threadIdx.x & 15;
    int r0 = rowTile + tr * 8, c0 = colTile + tc * 8;
#pragma unroll
    for (int m = 0; m < 8; m++)
#pragma unroll
        for (int p = 0; p < 4; p++) {
            float2 v = unpack2(acc[m][p]);
            *(float2*)&O[(size_t)(r0 + m) * DDIM + c0 + 2 * p] = v;
        }
}

// ---------------- launch ----------------------------------------------------
extern "C" void kernel_launch(void* const* d_in, const int* in_sizes, int n_in,
                              void* d_out, int out_size)
{
    const float* x  = (const float*)d_in[0];
    const float* Wq = (const float*)d_in[1];
    const float* Wk = (const float*)d_in[2];
    const float* Wv = (const float*)d_in[3];
    const float* P  = (const float*)d_in[4];
    const float* R  = (const float*)d_in[5];
    const float* tq = (const float*)d_in[6];
    const float* tk = (const float*)d_in[7];
    const float* tv = (const float*)d_in[8];
    float* out = (float*)d_out;

    bias_kernel<<<TWO_N / 256, 256>>>(R);
    proj_kernel<<<dim3(DDIM / 128, (BATCH * NSEQ) / 128, 3), 256>>>(x, Wq, Wk, Wv, tq, tk, tv);
    scores_kernel<<<dim3(NSEQ / 128, NSEQ / 128, BATCH), 256>>>(P);
    softmax_kernel<<<dim3(BATCH * NSEQ), 256>>>();
    out_kernel<<<dim3(DDIM / 128, NSEQ / 128, BATCH), 256>>>(out);
}

// round 4
// speedup vs baseline: 2.3641x; 2.3641x over previous
#include <cuda_runtime.h>
#include <cuda_bf16.h>
#include <cstdint>

#define NSEQ 2048
#define DDIM 1024
#define BATCH 8
#define TWO_N (2*NSEQ)
#define MTOT (BATCH*NSEQ)          // 16384 flat rows

// ------------------------- scratch (__device__ globals) ---------------------
__device__ __nv_bfloat16 g_xh[(size_t)MTOT*DDIM];
__device__ __nv_bfloat16 g_xl[(size_t)MTOT*DDIM];
__device__ __nv_bfloat16 g_wth[3*(size_t)DDIM*DDIM];   // W^T hi, [which][dout][din]
__device__ __nv_bfloat16 g_wtl[3*(size_t)DDIM*DDIM];
__device__ __nv_bfloat16 g_qh[(size_t)MTOT*DDIM];      // q[n][d]
__device__ __nv_bfloat16 g_ql[(size_t)MTOT*DDIM];
__device__ __nv_bfloat16 g_kh[(size_t)MTOT*DDIM];
__device__ __nv_bfloat16 g_kl[(size_t)MTOT*DDIM];
__device__ __nv_bfloat16 g_vth[(size_t)BATCH*DDIM*NSEQ]; // v^T [b][e][m]
__device__ __nv_bfloat16 g_vtl[(size_t)BATCH*DDIM*NSEQ];
__device__ float         g_s [(size_t)BATCH*NSEQ*NSEQ];  // scores fp32
__device__ __nv_bfloat16 g_ah[(size_t)BATCH*NSEQ*NSEQ];  // softmax hi/lo
__device__ __nv_bfloat16 g_al[(size_t)BATCH*NSEQ*NSEQ];
__device__ float         g_c [TWO_N];

// ------------------------------ PTX helpers --------------------------------
__device__ __forceinline__ uint32_t smem_u32(const void* p) {
    uint32_t a;
    asm("{ .reg .u64 t; cvta.to.shared.u64 t, %1; cvt.u32.u64 %0, t; }" : "=r"(a) : "l"(p));
    return a;
}
__device__ __forceinline__ void cp_async16(uint32_t dst, const void* src) {
    asm volatile("cp.async.cg.shared.global [%0], [%1], 16;" :: "r"(dst), "l"(src));
}
#define CP_COMMIT() asm volatile("cp.async.commit_group;")

__device__ __forceinline__ void ldsm4(uint32_t (&r)[4], uint32_t addr) {
    asm volatile("ldmatrix.sync.aligned.m8n8.x4.shared.b16 {%0,%1,%2,%3}, [%4];"
        : "=r"(r[0]), "=r"(r[1]), "=r"(r[2]), "=r"(r[3]) : "r"(addr));
}
__device__ __forceinline__ void ldsm2(uint32_t (&r)[2], uint32_t addr) {
    asm volatile("ldmatrix.sync.aligned.m8n8.x2.shared.b16 {%0,%1}, [%2];"
        : "=r"(r[0]), "=r"(r[1]) : "r"(addr));
}
__device__ __forceinline__ void mma16816(float (&c)[4], const uint32_t (&a)[4],
                                         const uint32_t (&b)[2]) {
    asm volatile("mma.sync.aligned.m16n8k16.row.col.f32.bf16.bf16.f32 "
        "{%0,%1,%2,%3}, {%4,%5,%6,%7}, {%8,%9}, {%0,%1,%2,%3};"
        : "+f"(c[0]), "+f"(c[1]), "+f"(c[2]), "+f"(c[3])
        : "r"(a[0]), "r"(a[1]), "r"(a[2]), "r"(a[3]), "r"(b[0]), "r"(b[1]));
}

// ---------------------- split helpers --------------------------------------
__device__ __forceinline__ void split_bf16(float v, __nv_bfloat16& h, __nv_bfloat16& l) {
    h = __float2bfloat16(v);
    l = __float2bfloat16(v - __bfloat162float(h));
}

// ---------------------- GEMM core -------------------------------------------
// C[128 x 128] = sum over 3 passes: Alist[p][rowTile..+128][:K] * Blist[p][colTile..+128][:K]^T
// A,B row-major bf16 with row stride K. 8 warps, warp grid 4(M) x 2(N), warp
// tile 32x64 via 2x8 m16n8k16 mma. acc[im][in][4] per thread.
#define STAGES 4
#define APITCH 40                     // halves per smem row (80 B)
#define TILEB  (128*APITCH*2)         // 10240 B
#define STAGEB (2*TILEB)              // 20480 B
#define SMEMB  (STAGES*STAGEB)        // 81920 B

__device__ __forceinline__ void gemm_mma(
    const __nv_bfloat16* A0, const __nv_bfloat16* A1, const __nv_bfloat16* A2,
    const __nv_bfloat16* B0, const __nv_bfloat16* B1, const __nv_bfloat16* B2,
    int K, size_t rowTile, size_t colTile, uint32_t sbase, float acc[2][8][4])
{
    const int tid  = threadIdx.x;
    const int lane = tid & 31;
    const int warp = tid >> 5;
    const int wm = warp & 3;          // 0..3 -> M offset wm*32
    const int wn = warp >> 2;         // 0..1 -> N offset wn*64
    const int KC  = K >> 5;           // 32-wide k chunks per pass
    const int NIT = 3 * KC;

#pragma unroll
    for (int im = 0; im < 2; im++)
#pragma unroll
        for (int in = 0; in < 8; in++)
#pragma unroll
            for (int j = 0; j < 4; j++) acc[im][in][j] = 0.f;

    auto issue = [&](int j) {
        int p  = j / KC;
        int kb = (j % KC) << 5;
        const __nv_bfloat16* Ap = (p == 0) ? A0 : (p == 1) ? A1 : A2;
        const __nv_bfloat16* Bp = (p == 0) ? B0 : (p == 1) ? B1 : B2;
        uint32_t sA = sbase + (j % STAGES) * STAGEB;
        uint32_t sB = sA + TILEB;
#pragma unroll
        for (int i = 0; i < 2; i++) {
            int c = tid + 256 * i;
            int row = c >> 2, seg = c & 3;
            cp_async16(sA + row * 80 + seg * 16,
                       Ap + (rowTile + row) * (size_t)K + kb + seg * 8);
        }
#pragma unroll
        for (int i = 0; i < 2; i++) {
            int c = tid + 256 * i;
            int row = c >> 2, seg = c & 3;
            cp_async16(sB + row * 80 + seg * 16,
                       Bp + (colTile + row) * (size_t)K + kb + seg * 8);
        }
        CP_COMMIT();
    };

    issue(0); issue(1); issue(2);

    // ldmatrix per-lane byte offsets inside a tile
    const uint32_t aOff = (uint32_t)((wm * 32 + (lane & 15)) * 80 + ((lane >> 4) & 1) * 16);
    const uint32_t bOff = (uint32_t)((wn * 64 + (lane & 7)) * 80 + ((lane >> 3) & 1) * 16);

    for (int it = 0; it < NIT; it++) {
        asm volatile("cp.async.wait_group 2;" ::: "memory");
        __syncthreads();
        if (it + STAGES - 1 < NIT) issue(it + STAGES - 1);

        uint32_t sA = sbase + (it % STAGES) * STAGEB;
        uint32_t sB = sA + TILEB;
#pragma unroll
        for (int ks = 0; ks < 2; ks++) {       // two k16 steps per 32-chunk
            uint32_t a0[4], a1[4], b[8][2];
            ldsm4(a0, sA + aOff + ks * 32);
            ldsm4(a1, sA + aOff + 16 * 80 + ks * 32);
#pragma unroll
            for (int in = 0; in < 8; in++)
                ldsm2(b[in], sB + bOff + in * 8 * 80 + ks * 32);
#pragma unroll
            for (int in = 0; in < 8; in++) {
                mma16816(acc[0][in], a0, b[in]);
                mma16816(acc[1][in], a1, b[in]);
            }
        }
    }
}

// ---------------------- kernel: Q/K projection ------------------------------
// C[n][d] = sum_din x[n][din] * WT[d][din]; store q/k hi/lo at [n][d] * tau
__global__ __launch_bounds__(256, 2) void k_projQK(const float* __restrict__ tq,
                                                   const float* __restrict__ tk)
{
    extern __shared__ char dsm[];
    uint32_t sbase = smem_u32(dsm);
    int z = blockIdx.z;
    size_t woff = (size_t)z * DDIM * DDIM;
    size_t rowTile = (size_t)blockIdx.y * 128;   // flat n
    size_t colTile = (size_t)blockIdx.x * 128;   // d

    float acc[2][8][4];
    gemm_mma(g_xh, g_xl, g_xh,
             g_wth + woff, g_wth + woff, g_wtl + woff,
             DDIM, rowTile, colTile, sbase, acc);

    float tau = z ? tk[0] : tq[0];
    __nv_bfloat16* Oh = z ? g_kh : g_qh;
    __nv_bfloat16* Ol = z ? g_kl : g_ql;
    int lane = threadIdx.x & 31, warp = threadIdx.x >> 5;
    int wm = warp & 3, wn = warp >> 2;
#pragma unroll
    for (int im = 0; im < 2; im++)
#pragma unroll
        for (int in = 0; in < 8; in++) {
            size_t n0 = rowTile + wm * 32 + im * 16 + (lane >> 2);
            size_t d  = colTile + wn * 64 + in * 8 + (lane & 3) * 2;
#pragma unroll
            for (int h = 0; h < 2; h++) {     // h=0 -> rows r, h=1 -> r+8
                size_t n = n0 + h * 8;
                float v0 = acc[im][in][2 * h + 0] * tau;
                float v1 = acc[im][in][2 * h + 1] * tau;
                __nv_bfloat16 h0, l0, h1, l1;
                split_bf16(v0, h0, l0); split_bf16(v1, h1, l1);
                __nv_bfloat162 hv; hv.x = h0; hv.y = h1;
                __nv_bfloat162 lv; lv.x = l0; lv.y = l1;
                *(__nv_bfloat162*)&Oh[n * DDIM + d] = hv;
                *(__nv_bfloat162*)&Ol[n * DDIM + d] = lv;
            }
        }
}

// ---------------------- kernel: V projection (transposed out) ---------------
// C[e][n] = sum_din WT_v[e][din] * x[n][din]; store vT[b][e][m] * tau
__global__ __launch_bounds__(256, 2) void k_projV(const float* __restrict__ tv)
{
    extern __shared__ char dsm[];
    uint32_t sbase = smem_u32(dsm);
    size_t rowTile = (size_t)blockIdx.y * 128;   // e
    size_t colTile = (size_t)blockIdx.x * 128;   // flat n
    size_t woff = 2 * (size_t)DDIM * DDIM;

    float acc[2][8][4];
    gemm_mma(g_wth + woff, g_wtl + woff, g_wth + woff,
             g_xh, g_xh, g_xl,
             DDIM, rowTile, colTile, sbase, acc);

    float tau = tv[0];
    int lane = threadIdx.x & 31, warp = threadIdx.x >> 5;
    int wm = warp & 3, wn = warp >> 2;
#pragma unroll
    for (int im = 0; im < 2; im++)
#pragma unroll
        for (int in = 0; in < 8; in++) {
            size_t e0 = rowTile + wm * 32 + im * 16 + (lane >> 2);
            size_t nf = colTile + wn * 64 + in * 8 + (lane & 3) * 2;
            size_t b = nf >> 11, m = nf & (NSEQ - 1);
#pragma unroll
            for (int h = 0; h < 2; h++) {
                size_t e = e0 + h * 8;
                float v0 = acc[im][in][2 * h + 0] * tau;
                float v1 = acc[im][in][2 * h + 1] * tau;
                __nv_bfloat16 h0, l0, h1, l1;
                split_bf16(v0, h0, l0); split_bf16(v1, h1, l1);
                __nv_bfloat162 hv; hv.x = h0; hv.y = h1;
                __nv_bfloat162 lv; lv.x = l0; lv.y = l1;
                size_t idx = (b * DDIM + e) * NSEQ + m;
                *(__nv_bfloat162*)&g_vth[idx] = hv;
                *(__nv_bfloat162*)&g_vtl[idx] = lv;
            }
        }
}

// ---------------------- kernel: scores --------------------------------------
// C[n][m] = q[n]·k[m];  S[b][n][m] = C*scale + P[n][m] + c[(n-m)&4095]
__global__ __launch_bounds__(256, 2) void k_scores(const float* __restrict__ P)
{
    extern __shared__ char dsm[];
    uint32_t sbase = smem_u32(dsm);
    int b = blockIdx.z;
    size_t rowTile = (size_t)b * NSEQ + blockIdx.y * 128;   // flat n into q
    size_t colTile = (size_t)b * NSEQ + blockIdx.x * 128;   // flat m into k

    float acc[2][8][4];
    gemm_mma(g_qh, g_ql, g_qh,
             g_kh, g_kh, g_kl,
             DDIM, rowTile, colTile, sbase, acc);

    const float scale = 0.03125f;
    float* S = g_s + (size_t)b * NSEQ * NSEQ;
    int lane = threadIdx.x & 31, warp = threadIdx.x >> 5;
    int wm = warp & 3, wn = warp >> 2;
#pragma unroll
    for (int im = 0; im < 2; im++)
#pragma unroll
        for (int in = 0; in < 8; in++) {
            int n0 = blockIdx.y * 128 + wm * 32 + im * 16 + (lane >> 2);
            int m  = blockIdx.x * 128 + wn * 64 + in * 8 + (lane & 3) * 2;
#pragma unroll
            for (int h = 0; h < 2; h++) {
                int n = n0 + h * 8;
                float2 pv = *(const float2*)&P[(size_t)n * NSEQ + m];
                float2 v;
                v.x = acc[im][in][2 * h + 0] * scale + pv.x + g_c[(n - m) & (TWO_N - 1)];
                v.y = acc[im][in][2 * h + 1] * scale + pv.y + g_c[(n - m - 1) & (TWO_N - 1)];
                *(float2*)&S[(size_t)n * NSEQ + m] = v;
            }
        }
}

// ---------------------- kernel: out = A @ v ---------------------------------
// C[n][e] = sum_m attn[n][m] * vT[e][m];  O[b][n][e]
__global__ __launch_bounds__(256, 2) void k_out(float* __restrict__ O)
{
    extern __shared__ char dsm[];
    uint32_t sbase = smem_u32(dsm);
    int b = blockIdx.z;
    size_t rowTile = (size_t)b * NSEQ + blockIdx.y * 128;   // flat n into attn
    size_t colTile = (size_t)b * DDIM + blockIdx.x * 128;   // flat e into vT

    float acc[2][8][4];
    gemm_mma(g_ah, g_al, g_ah,
             g_vth, g_vth, g_vtl,
             NSEQ, rowTile, colTile, sbase, acc);

    int lane = threadIdx.x & 31, warp = threadIdx.x >> 5;
    int wm = warp & 3, wn = warp >> 2;
#pragma unroll
    for (int im = 0; im < 2; im++)
#pragma unroll
        for (int in = 0; in < 8; in++) {
            int n0 = blockIdx.y * 128 + wm * 32 + im * 16 + (lane >> 2);
            int e  = blockIdx.x * 128 + wn * 64 + in * 8 + (lane & 3) * 2;
#pragma unroll
            for (int h = 0; h < 2; h++) {
                int n = n0 + h * 8;
                float2 v = make_float2(acc[im][in][2 * h + 0], acc[im][in][2 * h + 1]);
                *(float2*)&O[((size_t)b * NSEQ + n) * DDIM + e] = v;
            }
        }
}

// ---------------------- conversion kernels ----------------------------------
__global__ __launch_bounds__(256) void conv_x(const float* __restrict__ x) {
    size_t i = (size_t)blockIdx.x * 256 + threadIdx.x;
    float4 v = ((const float4*)x)[i];
    __nv_bfloat16 h[4], l[4];
    split_bf16(v.x, h[0], l[0]); split_bf16(v.y, h[1], l[1]);
    split_bf16(v.z, h[2], l[2]); split_bf16(v.w, h[3], l[3]);
    size_t o = i * 4;
#pragma unroll
    for (int k = 0; k < 4; k++) { g_xh[o + k] = h[k]; g_xl[o + k] = l[k]; }
}

__global__ void conv_wT(const float* __restrict__ Wq, const float* __restrict__ Wk,
                        const float* __restrict__ Wv) {
    __shared__ float t[32][33];
    int z = blockIdx.z;
    const float* W = (z == 0) ? Wq : (z == 1) ? Wk : Wv;
    int bx = blockIdx.x * 32, by = blockIdx.y * 32;
    int tx = threadIdx.x, ty = threadIdx.y;       // block (32, 8)
#pragma unroll
    for (int i = 0; i < 4; i++)
        t[ty + i * 8][tx] = W[(size_t)(by + ty + i * 8) * DDIM + bx + tx];
    __syncthreads();
    size_t base = (size_t)z * DDIM * DDIM;
#pragma unroll
    for (int i = 0; i < 4; i++) {
        int d = bx + ty + i * 8, k = by + tx;
        float v = t[tx][ty + i * 8];
        __nv_bfloat16 h, l; split_bf16(v, h, l);
        g_wth[base + (size_t)d * DDIM + k] = h;
        g_wtl[base + (size_t)d * DDIM + k] = l;
    }
}

// ---------------------- bias: c = real(ifft(R)) -----------------------------
__global__ __launch_bounds__(256) void bias_kernel(const float* __restrict__ R) {
    int t = blockIdx.x;
    int tid = threadIdx.x, lane = tid & 31, wid = tid >> 5;
    __shared__ float red[8];
    const float w = 6.283185307179586f / (float)TWO_N;
    float s = 0.f;
    for (int j = tid; j < TWO_N; j += 256)
        s += R[j] * cosf(w * (float)((j * t) & (TWO_N - 1)));
#pragma unroll
    for (int o = 16; o; o >>= 1) s += __shfl_xor_sync(0xFFFFFFFFu, s, o);
    if (lane == 0) red[wid] = s;
    __syncthreads();
    if (tid == 0) {
        float tot = 0.f;
#pragma unroll
        for (int i = 0; i < 8; i++) tot += red[i];
        g_c[t] = tot * (1.0f / (float)TWO_N);
    }
}

// ---------------------- softmax + bf16 split --------------------------------
__global__ __launch_bounds__(256) void softmax_kernel() {
    size_t row = blockIdx.x;
    float* p = g_s + row * NSEQ;
    __nv_bfloat16* ah = g_ah + row * NSEQ;
    __nv_bfloat16* al = g_al + row * NSEQ;
    int t = threadIdx.x, lane = t & 31, wid = t >> 5;
    __shared__ float red[8];

    float x[8];
#pragma unroll
    for (int i = 0; i < 8; i++) x[i] = p[t + i * 256];
    float m = x[0];
#pragma unroll
    for (int i = 1; i < 8; i++) m = fmaxf(m, x[i]);
#pragma unroll
    for (int o = 16; o; o >>= 1) m = fmaxf(m, __shfl_xor_sync(0xFFFFFFFFu, m, o));
    if (lane == 0) red[wid] = m;
    __syncthreads();
    float bm = red[0];
#pragma unroll
    for (int i = 1; i < 8; i++) bm = fmaxf(bm, red[i]);
    __syncthreads();
    float s = 0.f;
#pragma unroll
    for (int i = 0; i < 8; i++) { x[i] = expf(x[i] - bm); s += x[i]; }
#pragma unroll
    for (int o = 16; o; o >>= 1) s += __shfl_xor_sync(0xFFFFFFFFu, s, o);
    if (lane == 0) red[wid] = s;
    __syncthreads();
    float tot = red[0];
#pragma unroll
    for (int i = 1; i < 8; i++) tot += red[i];
    float inv = 1.0f / tot;
#pragma unroll
    for (int i = 0; i < 8; i++) {
        float a = x[i] * inv;
        __nv_bfloat16 h, l; split_bf16(a, h, l);
        ah[t + i * 256] = h;
        al[t + i * 256] = l;
    }
}

// ---------------------- launch ----------------------------------------------
extern "C" void kernel_launch(void* const* d_in, const int* in_sizes, int n_in,
                              void* d_out, int out_size)
{
    const float* x  = (const float*)d_in[0];
    const float* Wq = (const float*)d_in[1];
    const float* Wk = (const float*)d_in[2];
    const float* Wv = (const float*)d_in[3];
    const float* P  = (const float*)d_in[4];
    const float* R  = (const float*)d_in[5];
    const float* tq = (const float*)d_in[6];
    const float* tk = (const float*)d_in[7];
    const float* tv = (const float*)d_in[8];
    float* out = (float*)d_out;

    cudaFuncSetAttribute(k_projQK, cudaFuncAttributeMaxDynamicSharedMemorySize, SMEMB);
    cudaFuncSetAttribute(k_projV,  cudaFuncAttributeMaxDynamicSharedMemorySize, SMEMB);
    cudaFuncSetAttribute(k_scores, cudaFuncAttributeMaxDynamicSharedMemorySize, SMEMB);
    cudaFuncSetAttribute(k_out,    cudaFuncAttributeMaxDynamicSharedMemorySize, SMEMB);

    conv_x<<<(MTOT * DDIM) / 1024, 256>>>(x);
    conv_wT<<<dim3(32, 32, 3), dim3(32, 8)>>>(Wq, Wk, Wv);
    bias_kernel<<<TWO_N, 256>>>(R);

    k_projQK<<<dim3(DDIM / 128, MTOT / 128, 2), 256, SMEMB>>>(tq, tk);
    k_projV <<<dim3(MTOT / 128, DDIM / 128, 1), 256, SMEMB>>>(tv);
    k_scores<<<dim3(NSEQ / 128, NSEQ / 128, BATCH), 256, SMEMB>>>(P);
    softmax_kernel<<<dim3(BATCH * NSEQ), 256>>>();
    k_out   <<<dim3(DDIM / 128, NSEQ / 128, BATCH), 256, SMEMB>>>(out);
}

// round 5
// speedup vs baseline: 3.2755x; 1.3855x over previous
#include <cuda_runtime.h>
#include <cuda_bf16.h>
#include <cstdint>

#define NSEQ 2048
#define DDIM 1024
#define BATCH 8
#define TWO_N (2*NSEQ)
#define MTOT (BATCH*NSEQ)          // 16384 flat rows

// ------------------------- scratch (__device__ globals) ---------------------
__device__ __nv_bfloat16 g_xh[(size_t)MTOT*DDIM];
__device__ __nv_bfloat16 g_xl[(size_t)MTOT*DDIM];
__device__ __nv_bfloat16 g_wth[3*(size_t)DDIM*DDIM];   // W^T hi, [which][dout][din]
__device__ __nv_bfloat16 g_wtl[3*(size_t)DDIM*DDIM];
__device__ __nv_bfloat16 g_qh[(size_t)MTOT*DDIM];      // q[n][d]
__device__ __nv_bfloat16 g_ql[(size_t)MTOT*DDIM];
__device__ __nv_bfloat16 g_kh[(size_t)MTOT*DDIM];
__device__ __nv_bfloat16 g_kl[(size_t)MTOT*DDIM];
__device__ __nv_bfloat16 g_vth[(size_t)BATCH*DDIM*NSEQ]; // v^T [b][e][m]
__device__ __nv_bfloat16 g_vtl[(size_t)BATCH*DDIM*NSEQ];
__device__ float         g_s [(size_t)BATCH*NSEQ*NSEQ];  // scores fp32
__device__ __nv_bfloat16 g_ah[(size_t)BATCH*NSEQ*NSEQ];  // softmax hi/lo
__device__ __nv_bfloat16 g_al[(size_t)BATCH*NSEQ*NSEQ];
__device__ float         g_c [TWO_N];

// ------------------------------ PTX helpers --------------------------------
__device__ __forceinline__ uint32_t smem_u32(const void* p) {
    uint32_t a;
    asm("{ .reg .u64 t; cvta.to.shared.u64 t, %1; cvt.u32.u64 %0, t; }" : "=r"(a) : "l"(p));
    return a;
}
__device__ __forceinline__ void cp_async16(uint32_t dst, const void* src) {
    asm volatile("cp.async.cg.shared.global [%0], [%1], 16;" :: "r"(dst), "l"(src));
}
#define CP_COMMIT() asm volatile("cp.async.commit_group;")

__device__ __forceinline__ void ldsm4(uint32_t (&r)[4], uint32_t addr) {
    asm volatile("ldmatrix.sync.aligned.m8n8.x4.shared.b16 {%0,%1,%2,%3}, [%4];"
        : "=r"(r[0]), "=r"(r[1]), "=r"(r[2]), "=r"(r[3]) : "r"(addr));
}
__device__ __forceinline__ void mma16816(float (&c)[4], const uint32_t (&a)[4],
                                         uint32_t b0, uint32_t b1) {
    asm volatile("mma.sync.aligned.m16n8k16.row.col.f32.bf16.bf16.f32 "
        "{%0,%1,%2,%3}, {%4,%5,%6,%7}, {%8,%9}, {%0,%1,%2,%3};"
        : "+f"(c[0]), "+f"(c[1]), "+f"(c[2]), "+f"(c[3])
        : "r"(a[0]), "r"(a[1]), "r"(a[2]), "r"(a[3]), "r"(b0), "r"(b1));
}

// ---------------------- split helpers --------------------------------------
__device__ __forceinline__ void split_bf16(float v, __nv_bfloat16& h, __nv_bfloat16& l) {
    h = __float2bfloat16(v);
    l = __float2bfloat16(v - __bfloat162float(h));
}

// ---------------------- GEMM core -------------------------------------------
// C[128 x 128] = sum over 3 passes: Alist[p][rowTile..+128][:K] * Blist[p][colTile..+128][:K]^T
// A,B row-major bf16, row stride K. BK=64 (128B rows, XOR-swizzled), 3 stages.
// 8 warps, warp grid 4(M) x 2(N), warp tile 32x64 via 2x8 m16n8k16.
#define STAGES 3
#define TILEB  (128*128)              // 16384 B per tile
#define STAGEB (2*TILEB)              // 32768 B (A + B)
#define SMEMB  (STAGES*STAGEB)        // 98304 B

// physical smem offset for (row, 16B-seg) with bank swizzle
#define SWZ(row, seg) ((row) * 128 + ((((seg) ^ ((row) & 7))) << 4))

__device__ __forceinline__ void gemm_mma(
    const __nv_bfloat16* A0, const __nv_bfloat16* A1, const __nv_bfloat16* A2,
    const __nv_bfloat16* B0, const __nv_bfloat16* B1, const __nv_bfloat16* B2,
    int K, size_t rowTile, size_t colTile, uint32_t sbase, float acc[2][8][4])
{
    const int tid  = threadIdx.x;
    const int lane = tid & 31;
    const int warp = tid >> 5;
    const int wm = warp & 3;          // M offset wm*32
    const int wn = warp >> 2;         // N offset wn*64
    const int KC  = K >> 6;           // 64-wide k chunks per pass
    const int NIT = 3 * KC;

#pragma unroll
    for (int im = 0; im < 2; im++)
#pragma unroll
        for (int in = 0; in < 8; in++)
#pragma unroll
            for (int j = 0; j < 4; j++) acc[im][in][j] = 0.f;

    auto issue = [&](int j) {
        int p  = j / KC;
        int kb = (j % KC) << 6;
        const __nv_bfloat16* Ap = (p == 0) ? A0 : (p == 1) ? A1 : A2;
        const __nv_bfloat16* Bp = (p == 0) ? B0 : (p == 1) ? B1 : B2;
        uint32_t sA = sbase + (j % STAGES) * STAGEB;
        uint32_t sB = sA + TILEB;
#pragma unroll
        for (int i = 0; i < 4; i++) {
            int c = tid + 256 * i;            // 0..1023
            int row = c >> 3, seg = c & 7;
            cp_async16(sA + SWZ(row, seg),
                       Ap + (rowTile + row) * (size_t)K + kb + seg * 8);
        }
#pragma unroll
        for (int i = 0; i < 4; i++) {
            int c = tid + 256 * i;
            int row = c >> 3, seg = c & 7;
            cp_async16(sB + SWZ(row, seg),
                       Bp + (colTile + row) * (size_t)K + kb + seg * 8);
        }
        CP_COMMIT();
    };

    issue(0); issue(1);

    // ldmatrix lane decomposition (g = lane>>3)
    const uint32_t rm    = lane & 7;
    const uint32_t aRow0 = (uint32_t)(wm * 32 + ((lane >> 3) & 1) * 8 + rm) * 128;
    const uint32_t aColg = (uint32_t)(lane >> 4);          // g>>1
    const uint32_t bRow0 = (uint32_t)(wn * 64 + (lane >> 4) * 8 + rm) * 128;
    const uint32_t bColg = (uint32_t)((lane >> 3) & 1);    // g&1

    for (int it = 0; it < NIT; it++) {
        if (it + 1 < NIT) asm volatile("cp.async.wait_group 1;" ::: "memory");
        else              asm volatile("cp.async.wait_group 0;" ::: "memory");
        __syncthreads();
        if (it + 2 < NIT) issue(it + 2);

        uint32_t sA = sbase + (it % STAGES) * STAGEB;
        uint32_t sB = sA + TILEB;
#pragma unroll
        for (int ks = 0; ks < 4; ks++) {       // four k16 steps per 64-chunk
            uint32_t aC = (((uint32_t)(ks * 2) + aColg) ^ rm) << 4;
            uint32_t bC = (((uint32_t)(ks * 2) + bColg) ^ rm) << 4;
            uint32_t a0[4], a1[4], b[4][4];
            ldsm4(a0, sA + aRow0 + aC);
            ldsm4(a1, sA + aRow0 + 16 * 128 + aC);
#pragma unroll
            for (int inp = 0; inp < 4; inp++)
                ldsm4(b[inp], sB + bRow0 + inp * 16 * 128 + bC);
#pragma unroll
            for (int inp = 0; inp < 4; inp++) {
                mma16816(acc[0][inp * 2 + 0], a0, b[inp][0], b[inp][1]);
                mma16816(acc[1][inp * 2 + 0], a1, b[inp][0], b[inp][1]);
                mma16816(acc[0][inp * 2 + 1], a0, b[inp][2], b[inp][3]);
                mma16816(acc[1][inp * 2 + 1], a1, b[inp][2], b[inp][3]);
            }
        }
    }
}

// ---------------------- kernel: Q/K projection ------------------------------
__global__ __launch_bounds__(256, 2) void k_projQK(const float* __restrict__ tq,
                                                   const float* __restrict__ tk)
{
    extern __shared__ char dsm[];
    uint32_t sbase = smem_u32(dsm);
    int z = blockIdx.z;
    size_t woff = (size_t)z * DDIM * DDIM;
    size_t rowTile = (size_t)blockIdx.y * 128;   // flat n
    size_t colTile = (size_t)blockIdx.x * 128;   // d

    float acc[2][8][4];
    gemm_mma(g_xh, g_xl, g_xh,
             g_wth + woff, g_wth + woff, g_wtl + woff,
             DDIM, rowTile, colTile, sbase, acc);

    float tau = z ? tk[0] : tq[0];
    __nv_bfloat16* Oh = z ? g_kh : g_qh;
    __nv_bfloat16* Ol = z ? g_kl : g_ql;
    int lane = threadIdx.x & 31, warp = threadIdx.x >> 5;
    int wm = warp & 3, wn = warp >> 2;
#pragma unroll
    for (int im = 0; im < 2; im++)
#pragma unroll
        for (int in = 0; in < 8; in++) {
            size_t n0 = rowTile + wm * 32 + im * 16 + (lane >> 2);
            size_t d  = colTile + wn * 64 + in * 8 + (lane & 3) * 2;
#pragma unroll
            for (int h = 0; h < 2; h++) {
                size_t n = n0 + h * 8;
                float v0 = acc[im][in][2 * h + 0] * tau;
                float v1 = acc[im][in][2 * h + 1] * tau;
                __nv_bfloat16 h0, l0, h1, l1;
                split_bf16(v0, h0, l0); split_bf16(v1, h1, l1);
                __nv_bfloat162 hv; hv.x = h0; hv.y = h1;
                __nv_bfloat162 lv; lv.x = l0; lv.y = l1;
                *(__nv_bfloat162*)&Oh[n * DDIM + d] = hv;
                *(__nv_bfloat162*)&Ol[n * DDIM + d] = lv;
            }
        }
}

// ---------------------- kernel: V projection (transposed out) ---------------
__global__ __launch_bounds__(256, 2) void k_projV(const float* __restrict__ tv)
{
    extern __shared__ char dsm[];
    uint32_t sbase = smem_u32(dsm);
    size_t rowTile = (size_t)blockIdx.y * 128;   // e
    size_t colTile = (size_t)blockIdx.x * 128;   // flat n
    size_t woff = 2 * (size_t)DDIM * DDIM;

    float acc[2][8][4];
    gemm_mma(g_wth + woff, g_wtl + woff, g_wth + woff,
             g_xh, g_xh, g_xl,
             DDIM, rowTile, colTile, sbase, acc);

    float tau = tv[0];
    int lane = threadIdx.x & 31, warp = threadIdx.x >> 5;
    int wm = warp & 3, wn = warp >> 2;
#pragma unroll
    for (int im = 0; im < 2; im++)
#pragma unroll
        for (int in = 0; in < 8; in++) {
            size_t e0 = rowTile + wm * 32 + im * 16 + (lane >> 2);
            size_t nf = colTile + wn * 64 + in * 8 + (lane & 3) * 2;
            size_t b = nf >> 11, m = nf & (NSEQ - 1);
#pragma unroll
            for (int h = 0; h < 2; h++) {
                size_t e = e0 + h * 8;
                float v0 = acc[im][in][2 * h + 0] * tau;
                float v1 = acc[im][in][2 * h + 1] * tau;
                __nv_bfloat16 h0, l0, h1, l1;
                split_bf16(v0, h0, l0); split_bf16(v1, h1, l1);
                __nv_bfloat162 hv; hv.x = h0; hv.y = h1;
                __nv_bfloat162 lv; lv.x = l0; lv.y = l1;
                size_t idx = (b * DDIM + e) * NSEQ + m;
                *(__nv_bfloat162*)&g_vth[idx] = hv;
                *(__nv_bfloat162*)&g_vtl[idx] = lv;
            }
        }
}

// ---------------------- kernel: scores --------------------------------------
__global__ __launch_bounds__(256, 2) void k_scores(const float* __restrict__ P)
{
    extern __shared__ char dsm[];
    uint32_t sbase = smem_u32(dsm);
    int b = blockIdx.z;
    size_t rowTile = (size_t)b * NSEQ + blockIdx.y * 128;   // flat n into q
    size_t colTile = (size_t)b * NSEQ + blockIdx.x * 128;   // flat m into k

    float acc[2][8][4];
    gemm_mma(g_qh, g_ql, g_qh,
             g_kh, g_kh, g_kl,
             DDIM, rowTile, colTile, sbase, acc);

    const float scale = 0.03125f;
    float* S = g_s + (size_t)b * NSEQ * NSEQ;
    int lane = threadIdx.x & 31, warp = threadIdx.x >> 5;
    int wm = warp & 3, wn = warp >> 2;
#pragma unroll
    for (int im = 0; im < 2; im++)
#pragma unroll
        for (int in = 0; in < 8; in++) {
            int n0 = blockIdx.y * 128 + wm * 32 + im * 16 + (lane >> 2);
            int m  = blockIdx.x * 128 + wn * 64 + in * 8 + (lane & 3) * 2;
#pragma unroll
            for (int h = 0; h < 2; h++) {
                int n = n0 + h * 8;
                float2 pv = *(const float2*)&P[(size_t)n * NSEQ + m];
                float2 v;
                v.x = acc[im][in][2 * h + 0] * scale + pv.x + g_c[(n - m) & (TWO_N - 1)];
                v.y = acc[im][in][2 * h + 1] * scale + pv.y + g_c[(n - m - 1) & (TWO_N - 1)];
                *(float2*)&S[(size_t)n * NSEQ + m] = v;
            }
        }
}

// ---------------------- kernel: out = A @ v ---------------------------------
__global__ __launch_bounds__(256, 2) void k_out(float* __restrict__ O)
{
    extern __shared__ char dsm[];
    uint32_t sbase = smem_u32(dsm);
    int b = blockIdx.z;
    size_t rowTile = (size_t)b * NSEQ + blockIdx.y * 128;   // flat n into attn
    size_t colTile = (size_t)b * DDIM + blockIdx.x * 128;   // flat e into vT

    float acc[2][8][4];
    gemm_mma(g_ah, g_al, g_ah,
             g_vth, g_vth, g_vtl,
             NSEQ, rowTile, colTile, sbase, acc);

    int lane = threadIdx.x & 31, warp = threadIdx.x >> 5;
    int wm = warp & 3, wn = warp >> 2;
#pragma unroll
    for (int im = 0; im < 2; im++)
#pragma unroll
        for (int in = 0; in < 8; in++) {
            int n0 = blockIdx.y * 128 + wm * 32 + im * 16 + (lane >> 2);
            int e  = blockIdx.x * 128 + wn * 64 + in * 8 + (lane & 3) * 2;
#pragma unroll
            for (int h = 0; h < 2; h++) {
                int n = n0 + h * 8;
                float2 v = make_float2(acc[im][in][2 * h + 0], acc[im][in][2 * h + 1]);
                *(float2*)&O[((size_t)b * NSEQ + n) * DDIM + e] = v;
            }
        }
}

// ---------------------- conversion kernels ----------------------------------
__global__ __launch_bounds__(256) void conv_x(const float* __restrict__ x) {
    size_t i = (size_t)blockIdx.x * 256 + threadIdx.x;
    float4 v = ((const float4*)x)[i];
    __nv_bfloat16 h[4], l[4];
    split_bf16(v.x, h[0], l[0]); split_bf16(v.y, h[1], l[1]);
    split_bf16(v.z, h[2], l[2]); split_bf16(v.w, h[3], l[3]);
    size_t o = i * 4;
#pragma unroll
    for (int k = 0; k < 4; k++) { g_xh[o + k] = h[k]; g_xl[o + k] = l[k]; }
}

__global__ void conv_wT(const float* __restrict__ Wq, const float* __restrict__ Wk,
                        const float* __restrict__ Wv) {
    __shared__ float t[32][33];
    int z = blockIdx.z;
    const float* W = (z == 0) ? Wq : (z == 1) ? Wk : Wv;
    int bx = blockIdx.x * 32, by = blockIdx.y * 32;
    int tx = threadIdx.x, ty = threadIdx.y;       // block (32, 8)
#pragma unroll
    for (int i = 0; i < 4; i++)
        t[ty + i * 8][tx] = W[(size_t)(by + ty + i * 8) * DDIM + bx + tx];
    __syncthreads();
    size_t base = (size_t)z * DDIM * DDIM;
#pragma unroll
    for (int i = 0; i < 4; i++) {
        int d = bx + ty + i * 8, k = by + tx;
        float v = t[tx][ty + i * 8];
        __nv_bfloat16 h, l; split_bf16(v, h, l);
        g_wth[base + (size_t)d * DDIM + k] = h;
        g_wtl[base + (size_t)d * DDIM + k] = l;
    }
}

// ---------------------- bias: c = real(ifft(R)) -----------------------------
__global__ __launch_bounds__(256) void bias_kernel(const float* __restrict__ R) {
    int t = blockIdx.x;
    int tid = threadIdx.x, lane = tid & 31, wid = tid >> 5;
    __shared__ float red[8];
    const float w = 6.283185307179586f / (float)TWO_N;
    float s = 0.f;
    for (int j = tid; j < TWO_N; j += 256)
        s += R[j] * cosf(w * (float)((j * t) & (TWO_N - 1)));
#pragma unroll
    for (int o = 16; o; o >>= 1) s += __shfl_xor_sync(0xFFFFFFFFu, s, o);
    if (lane == 0) red[wid] = s;
    __syncthreads();
    if (tid == 0) {
        float tot = 0.f;
#pragma unroll
        for (int i = 0; i < 8; i++) tot += red[i];
        g_c[t] = tot * (1.0f / (float)TWO_N);
    }
}

// ---------------------- softmax + bf16 split --------------------------------
__global__ __launch_bounds__(256) void softmax_kernel() {
    size_t row = blockIdx.x;
    float* p = g_s + row * NSEQ;
    __nv_bfloat16* ah = g_ah + row * NSEQ;
    __nv_bfloat16* al = g_al + row * NSEQ;
    int t = threadIdx.x, lane = t & 31, wid = t >> 5;
    __shared__ float red[8];

    float x[8];
#pragma unroll
    for (int i = 0; i < 8; i++) x[i] = p[t + i * 256];
    float m = x[0];
#pragma unroll
    for (int i = 1; i < 8; i++) m = fmaxf(m, x[i]);
#pragma unroll
    for (int o = 16; o; o >>= 1) m = fmaxf(m, __shfl_xor_sync(0xFFFFFFFFu, m, o));
    if (lane == 0) red[wid] = m;
    __syncthreads();
    float bm = red[0];
#pragma unroll
    for (int i = 1; i < 8; i++) bm = fmaxf(bm, red[i]);
    __syncthreads();
    float s = 0.f;
#pragma unroll
    for (int i = 0; i < 8; i++) { x[i] = expf(x[i] - bm); s += x[i]; }
#pragma unroll
    for (int o = 16; o; o >>= 1) s += __shfl_xor_sync(0xFFFFFFFFu, s, o);
    if (lane == 0) red[wid] = s;
    __syncthreads();
    float tot = red[0];
#pragma unroll
    for (int i = 1; i < 8; i++) tot += red[i];
    float inv = 1.0f / tot;
#pragma unroll
    for (int i = 0; i < 8; i++) {
        float a = x[i] * inv;
        __nv_bfloat16 h, l; split_bf16(a, h, l);
        ah[t + i * 256] = h;
        al[t + i * 256] = l;
    }
}

// ---------------------- launch ----------------------------------------------
extern "C" void kernel_launch(void* const* d_in, const int* in_sizes, int n_in,
                              void* d_out, int out_size)
{
    const float* x  = (const float*)d_in[0];
    const float* Wq = (const float*)d_in[1];
    const float* Wk = (const float*)d_in[2];
    const float* Wv = (const float*)d_in[3];
    const float* P  = (const float*)d_in[4];
    const float* R  = (const float*)d_in[5];
    const float* tq = (const float*)d_in[6];
    const float* tk = (const float*)d_in[7];
    const float* tv = (const float*)d_in[8];
    float* out = (float*)d_out;

    cudaFuncSetAttribute(k_projQK, cudaFuncAttributeMaxDynamicSharedMemorySize, SMEMB);
    cudaFuncSetAttribute(k_projV,  cudaFuncAttributeMaxDynamicSharedMemorySize, SMEMB);
    cudaFuncSetAttribute(k_scores, cudaFuncAttributeMaxDynamicSharedMemorySize, SMEMB);
    cudaFuncSetAttribute(k_out,    cudaFuncAttributeMaxDynamicSharedMemorySize, SMEMB);

    conv_x<<<(MTOT * DDIM) / 1024, 256>>>(x);
    conv_wT<<<dim3(32, 32, 3), dim3(32, 8)>>>(Wq, Wk, Wv);
    bias_kernel<<<TWO_N, 256>>>(R);

    k_projQK<<<dim3(DDIM / 128, MTOT / 128, 2), 256, SMEMB>>>(tq, tk);
    k_projV <<<dim3(MTOT / 128, DDIM / 128, 1), 256, SMEMB>>>(tv);
    k_scores<<<dim3(NSEQ / 128, NSEQ / 128, BATCH), 256, SMEMB>>>(P);
    softmax_kernel<<<dim3(BATCH * NSEQ), 256>>>();
    k_out   <<<dim3(DDIM / 128, NSEQ / 128, BATCH), 256, SMEMB>>>(out);
}

// round 6
// speedup vs baseline: 3.9188x; 1.1964x over previous
#include <cuda_runtime.h>
#include <cuda_fp16.h>
#include <cstdint>

#define NSEQ 2048
#define DDIM 1024
#define BATCH 8
#define TWO_N (2*NSEQ)
#define MTOT (BATCH*NSEQ)          // 16384 flat rows

// ------------------------- scratch (__device__ globals) ---------------------
__device__ __half g_xh [(size_t)MTOT*DDIM];
__device__ __half g_xl [(size_t)MTOT*DDIM];
__device__ __half g_wth[3*(size_t)DDIM*DDIM];   // W^T hi, [which][dout][din]
__device__ __half g_wtl[3*(size_t)DDIM*DDIM];
__device__ __half g_qh [(size_t)MTOT*DDIM];      // q[n][d]
__device__ __half g_ql [(size_t)MTOT*DDIM];
__device__ __half g_kh [(size_t)MTOT*DDIM];      // k hi only (2-product scores)
__device__ __half g_vth[(size_t)BATCH*DDIM*NSEQ];// v^T hi only [b][e][m]
__device__ float  g_s  [(size_t)BATCH*NSEQ*NSEQ];// scores fp32
__device__ __half g_ah [(size_t)BATCH*NSEQ*NSEQ];// softmax hi/lo
__device__ __half g_al [(size_t)BATCH*NSEQ*NSEQ];
__device__ float  g_c  [TWO_N];

// ------------------------------ PTX helpers --------------------------------
__device__ __forceinline__ uint32_t smem_u32(const void* p) {
    uint32_t a;
    asm("{ .reg .u64 t; cvta.to.shared.u64 t, %1; cvt.u32.u64 %0, t; }" : "=r"(a) : "l"(p));
    return a;
}
__device__ __forceinline__ void cp_async16(uint32_t dst, const void* src) {
    asm volatile("cp.async.cg.shared.global [%0], [%1], 16;" :: "r"(dst), "l"(src));
}
#define CP_COMMIT() asm volatile("cp.async.commit_group;")

__device__ __forceinline__ void ldsm4(uint32_t (&r)[4], uint32_t addr) {
    asm volatile("ldmatrix.sync.aligned.m8n8.x4.shared.b16 {%0,%1,%2,%3}, [%4];"
        : "=r"(r[0]), "=r"(r[1]), "=r"(r[2]), "=r"(r[3]) : "r"(addr));
}
__device__ __forceinline__ void mma16816(float (&c)[4], const uint32_t (&a)[4],
                                         uint32_t b0, uint32_t b1) {
    asm volatile("mma.sync.aligned.m16n8k16.row.col.f32.f16.f16.f32 "
        "{%0,%1,%2,%3}, {%4,%5,%6,%7}, {%8,%9}, {%0,%1,%2,%3};"
        : "+f"(c[0]), "+f"(c[1]), "+f"(c[2]), "+f"(c[3])
        : "r"(a[0]), "r"(a[1]), "r"(a[2]), "r"(a[3]), "r"(b0), "r"(b1));
}

// ---------------------- split helpers --------------------------------------
__device__ __forceinline__ void split_f16(float v, __half& h, __half& l) {
    h = __float2half_rn(v);
    l = __float2half_rn(v - __half2float(h));
}

// ---------------------- GEMM core -------------------------------------------
// C[128 x 128] = sum over NP passes: Ap[p][rowTile..+128][:K] * Bp[p][colTile..+128][:K]^T
// A,B row-major fp16, row stride K. BK=64 (128B rows, XOR-swizzled), 3 stages.
// 8 warps, warp grid 4(M) x 2(N), warp tile 32x64 via 2x8 m16n8k16.
#define STAGES 3
#define TILEB  (128*128)              // 16384 B per tile
#define STAGEB (2*TILEB)              // 32768 B (A + B)
#define SMEMB  (STAGES*STAGEB)        // 98304 B

// physical smem offset for (row, 16B-seg) with bank swizzle
#define SWZ(row, seg) ((row) * 128 + ((((seg) ^ ((row) & 7))) << 4))

template<int NP>
__device__ __forceinline__ void gemm_mma(
    const __half* const* Ap, const __half* const* Bp,
    int K, size_t rowTile, size_t colTile, uint32_t sbase, float acc[2][8][4])
{
    const int tid  = threadIdx.x;
    const int lane = tid & 31;
    const int warp = tid >> 5;
    const int wm = warp & 3;          // M offset wm*32
    const int wn = warp >> 2;         // N offset wn*64
    const int KC  = K >> 6;           // 64-wide k chunks per pass
    const int NIT = NP * KC;

#pragma unroll
    for (int im = 0; im < 2; im++)
#pragma unroll
        for (int in = 0; in < 8; in++)
#pragma unroll
            for (int j = 0; j < 4; j++) acc[im][in][j] = 0.f;

    auto issue = [&](int j) {
        int p  = j / KC;
        int kb = (j % KC) << 6;
        const __half* A = Ap[p];
        const __half* B = Bp[p];
        uint32_t sA = sbase + (j % STAGES) * STAGEB;
        uint32_t sB = sA + TILEB;
#pragma unroll
        for (int i = 0; i < 4; i++) {
            int c = tid + 256 * i;            // 0..1023
            int row = c >> 3, seg = c & 7;
            cp_async16(sA + SWZ(row, seg),
                       A + (rowTile + row) * (size_t)K + kb + seg * 8);
        }
#pragma unroll
        for (int i = 0; i < 4; i++) {
            int c = tid + 256 * i;
            int row = c >> 3, seg = c & 7;
            cp_async16(sB + SWZ(row, seg),
                       B + (colTile + row) * (size_t)K + kb + seg * 8);
        }
        CP_COMMIT();
    };

    issue(0); issue(1);

    // ldmatrix lane decomposition (g = lane>>3)
    const uint32_t rm    = lane & 7;
    const uint32_t aRow0 = (uint32_t)(wm * 32 + ((lane >> 3) & 1) * 8 + rm) * 128;
    const uint32_t aColg = (uint32_t)(lane >> 4);          // g>>1
    const uint32_t bRow0 = (uint32_t)(wn * 64 + (lane >> 4) * 8 + rm) * 128;
    const uint32_t bColg = (uint32_t)((lane >> 3) & 1);    // g&1

    for (int it = 0; it < NIT; it++) {
        if (it + 1 < NIT) asm volatile("cp.async.wait_group 1;" ::: "memory");
        else              asm volatile("cp.async.wait_group 0;" ::: "memory");
        __syncthreads();
        if (it + 2 < NIT) issue(it + 2);

        uint32_t sA = sbase + (it % STAGES) * STAGEB;
        uint32_t sB = sA + TILEB;
#pragma unroll
        for (int ks = 0; ks < 4; ks++) {       // four k16 steps per 64-chunk
            uint32_t aC = (((uint32_t)(ks * 2) + aColg) ^ rm) << 4;
            uint32_t bC = (((uint32_t)(ks * 2) + bColg) ^ rm) << 4;
            uint32_t a0[4], a1[4], b[4][4];
            ldsm4(a0, sA + aRow0 + aC);
            ldsm4(a1, sA + aRow0 + 16 * 128 + aC);
#pragma unroll
            for (int inp = 0; inp < 4; inp++)
                ldsm4(b[inp], sB + bRow0 + inp * 16 * 128 + bC);
#pragma unroll
            for (int inp = 0; inp < 4; inp++) {
                mma16816(acc[0][inp * 2 + 0], a0, b[inp][0], b[inp][1]);
                mma16816(acc[1][inp * 2 + 0], a1, b[inp][0], b[inp][1]);
                mma16816(acc[0][inp * 2 + 1], a0, b[inp][2], b[inp][3]);
                mma16816(acc[1][inp * 2 + 1], a1, b[inp][2], b[inp][3]);
            }
        }
    }
}

// ---------------------- kernel: Q/K projection ------------------------------
// C[n][d] = x[n]·Wcol[d]; q: store hi+lo, k: store hi only (both * tau)
__global__ __launch_bounds__(256, 2) void k_projQK(const float* __restrict__ tq,
                                                   const float* __restrict__ tk)
{
    extern __shared__ char dsm[];
    uint32_t sbase = smem_u32(dsm);
    int z = blockIdx.z;
    size_t woff = (size_t)z * DDIM * DDIM;
    size_t rowTile = (size_t)blockIdx.y * 128;   // flat n
    size_t colTile = (size_t)blockIdx.x * 128;   // d

    const __half* Ap[3] = { g_xh, g_xl, g_xh };
    const __half* Bp[3] = { g_wth + woff, g_wth + woff, g_wtl + woff };
    float acc[2][8][4];
    gemm_mma<3>(Ap, Bp, DDIM, rowTile, colTile, sbase, acc);

    float tau = z ? tk[0] : tq[0];
    __half* Oh = z ? g_kh : g_qh;
    int lane = threadIdx.x & 31, warp = threadIdx.x >> 5;
    int wm = warp & 3, wn = warp >> 2;
#pragma unroll
    for (int im = 0; im < 2; im++)
#pragma unroll
        for (int in = 0; in < 8; in++) {
            size_t n0 = rowTile + wm * 32 + im * 16 + (lane >> 2);
            size_t d  = colTile + wn * 64 + in * 8 + (lane & 3) * 2;
#pragma unroll
            for (int h = 0; h < 2; h++) {
                size_t n = n0 + h * 8;
                float v0 = acc[im][in][2 * h + 0] * tau;
                float v1 = acc[im][in][2 * h + 1] * tau;
                __half h0, l0, h1, l1;
                split_f16(v0, h0, l0); split_f16(v1, h1, l1);
                __half2 hv; hv.x = h0; hv.y = h1;
                *(__half2*)&Oh[n * DDIM + d] = hv;
                if (z == 0) {
                    __half2 lv; lv.x = l0; lv.y = l1;
                    *(__half2*)&g_ql[n * DDIM + d] = lv;
                }
            }
        }
}

// ---------------------- kernel: V projection (transposed out, hi only) ------
__global__ __launch_bounds__(256, 2) void k_projV(const float* __restrict__ tv)
{
    extern __shared__ char dsm[];
    uint32_t sbase = smem_u32(dsm);
    size_t rowTile = (size_t)blockIdx.y * 128;   // e
    size_t colTile = (size_t)blockIdx.x * 128;   // flat n
    size_t woff = 2 * (size_t)DDIM * DDIM;

    const __half* Ap[3] = { g_wth + woff, g_wtl + woff, g_wth + woff };
    const __half* Bp[3] = { g_xh, g_xh, g_xl };
    float acc[2][8][4];
    gemm_mma<3>(Ap, Bp, DDIM, rowTile, colTile, sbase, acc);

    float tau = tv[0];
    int lane = threadIdx.x & 31, warp = threadIdx.x >> 5;
    int wm = warp & 3, wn = warp >> 2;
#pragma unroll
    for (int im = 0; im < 2; im++)
#pragma unroll
        for (int in = 0; in < 8; in++) {
            size_t e0 = rowTile + wm * 32 + im * 16 + (lane >> 2);
            size_t nf = colTile + wn * 64 + in * 8 + (lane & 3) * 2;
            size_t b = nf >> 11, m = nf & (NSEQ - 1);
#pragma unroll
            for (int h = 0; h < 2; h++) {
                size_t e = e0 + h * 8;
                __half2 hv;
                hv.x = __float2half_rn(acc[im][in][2 * h + 0] * tau);
                hv.y = __float2half_rn(acc[im][in][2 * h + 1] * tau);
                *(__half2*)&g_vth[(b * DDIM + e) * NSEQ + m] = hv;
            }
        }
}

// ---------------------- kernel: scores (2-product) --------------------------
// C[n][m] = q[n]·k[m];  S[b][n][m] = C*scale + P[n][m] + c[(n-m)&4095]
__global__ __launch_bounds__(256, 2) void k_scores(const float* __restrict__ P)
{
    extern __shared__ char dsm[];
    uint32_t sbase = smem_u32(dsm);
    int b = blockIdx.z;
    size_t rowTile = (size_t)b * NSEQ + blockIdx.y * 128;   // flat n into q
    size_t colTile = (size_t)b * NSEQ + blockIdx.x * 128;   // flat m into k

    const __half* Ap[2] = { g_qh, g_ql };
    const __half* Bp[2] = { g_kh, g_kh };
    float acc[2][8][4];
    gemm_mma<2>(Ap, Bp, DDIM, rowTile, colTile, sbase, acc);

    const float scale = 0.03125f;
    float* S = g_s + (size_t)b * NSEQ * NSEQ;
    int lane = threadIdx.x & 31, warp = threadIdx.x >> 5;
    int wm = warp & 3, wn = warp >> 2;
#pragma unroll
    for (int im = 0; im < 2; im++)
#pragma unroll
        for (int in = 0; in < 8; in++) {
            int n0 = blockIdx.y * 128 + wm * 32 + im * 16 + (lane >> 2);
            int m  = blockIdx.x * 128 + wn * 64 + in * 8 + (lane & 3) * 2;
#pragma unroll
            for (int h = 0; h < 2; h++) {
                int n = n0 + h * 8;
                float2 pv = *(const float2*)&P[(size_t)n * NSEQ + m];
                float2 v;
                v.x = acc[im][in][2 * h + 0] * scale + pv.x + g_c[(n - m) & (TWO_N - 1)];
                v.y = acc[im][in][2 * h + 1] * scale + pv.y + g_c[(n - m - 1) & (TWO_N - 1)];
                *(float2*)&S[(size_t)n * NSEQ + m] = v;
            }
        }
}

// ---------------------- kernel: out = A @ v (2-product) ---------------------
__global__ __launch_bounds__(256, 2) void k_out(float* __restrict__ O)
{
    extern __shared__ char dsm[];
    uint32_t sbase = smem_u32(dsm);
    int b = blockIdx.z;
    size_t rowTile = (size_t)b * NSEQ + blockIdx.y * 128;   // flat n into attn
    size_t colTile = (size_t)b * DDIM + blockIdx.x * 128;   // flat e into vT

    const __half* Ap[2] = { g_ah, g_al };
    const __half* Bp[2] = { g_vth, g_vth };
    float acc[2][8][4];
    gemm_mma<2>(Ap, Bp, NSEQ, rowTile, colTile, sbase, acc);

    int lane = threadIdx.x & 31, warp = threadIdx.x >> 5;
    int wm = warp & 3, wn = warp >> 2;
#pragma unroll
    for (int im = 0; im < 2; im++)
#pragma unroll
        for (int in = 0; in < 8; in++) {
            int n0 = blockIdx.y * 128 + wm * 32 + im * 16 + (lane >> 2);
            int e  = blockIdx.x * 128 + wn * 64 + in * 8 + (lane & 3) * 2;
#pragma unroll
            for (int h = 0; h < 2; h++) {
                int n = n0 + h * 8;
                float2 v = make_float2(acc[im][in][2 * h + 0], acc[im][in][2 * h + 1]);
                *(float2*)&O[((size_t)b * NSEQ + n) * DDIM + e] = v;
            }
        }
}

// ---------------------- conversion kernels ----------------------------------
__global__ __launch_bounds__(256) void conv_x(const float* __restrict__ x) {
    size_t i = (size_t)blockIdx.x * 256 + threadIdx.x;
    float4 v = ((const float4*)x)[i];
    __half h[4], l[4];
    split_f16(v.x, h[0], l[0]); split_f16(v.y, h[1], l[1]);
    split_f16(v.z, h[2], l[2]); split_f16(v.w, h[3], l[3]);
    size_t o = i * 4;
#pragma unroll
    for (int k = 0; k < 4; k++) { g_xh[o + k] = h[k]; g_xl[o + k] = l[k]; }
}

__global__ void conv_wT(const float* __restrict__ Wq, const float* __restrict__ Wk,
                        const float* __restrict__ Wv) {
    __shared__ float t[32][33];
    int z = blockIdx.z;
    const float* W = (z == 0) ? Wq : (z == 1) ? Wk : Wv;
    int bx = blockIdx.x * 32, by = blockIdx.y * 32;
    int tx = threadIdx.x, ty = threadIdx.y;       // block (32, 8)
#pragma unroll
    for (int i = 0; i < 4; i++)
        t[ty + i * 8][tx] = W[(size_t)(by + ty + i * 8) * DDIM + bx + tx];
    __syncthreads();
    size_t base = (size_t)z * DDIM * DDIM;
#pragma unroll
    for (int i = 0; i < 4; i++) {
        int d = bx + ty + i * 8, k = by + tx;
        float v = t[tx][ty + i * 8];
        __half h, l; split_f16(v, h, l);
        g_wth[base + (size_t)d * DDIM + k] = h;
        g_wtl[base + (size_t)d * DDIM + k] = l;
    }
}

// ---------------------- bias: c = real(ifft(R)) -----------------------------
__global__ __launch_bounds__(256) void bias_kernel(const float* __restrict__ R) {
    int t = blockIdx.x;
    int tid = threadIdx.x, lane = tid & 31, wid = tid >> 5;
    __shared__ float red[8];
    const float w = 6.283185307179586f / (float)TWO_N;
    float s = 0.f;
    for (int j = tid; j < TWO_N; j += 256)
        s += R[j] * cosf(w * (float)((j * t) & (TWO_N - 1)));
#pragma unroll
    for (int o = 16; o; o >>= 1) s += __shfl_xor_sync(0xFFFFFFFFu, s, o);
    if (lane == 0) red[wid] = s;
    __syncthreads();
    if (tid == 0) {
        float tot = 0.f;
#pragma unroll
        for (int i = 0; i < 8; i++) tot += red[i];
        g_c[t] = tot * (1.0f / (float)TWO_N);
    }
}

// ---------------------- softmax + fp16 split --------------------------------
__global__ __launch_bounds__(256) void softmax_kernel() {
    size_t row = blockIdx.x;
    float* p = g_s + row * NSEQ;
    __half* ah = g_ah + row * NSEQ;
    __half* al = g_al + row * NSEQ;
    int t = threadIdx.x, lane = t & 31, wid = t >> 5;
    __shared__ float red[8];

    float x[8];
#pragma unroll
    for (int i = 0; i < 8; i++) x[i] = p[t + i * 256];
    float m = x[0];
#pragma unroll
    for (int i = 1; i < 8; i++) m = fmaxf(m, x[i]);
#pragma unroll
    for (int o = 16; o; o >>= 1) m = fmaxf(m, __shfl_xor_sync(0xFFFFFFFFu, m, o));
    if (lane == 0) red[wid] = m;
    __syncthreads();
    float bm = red[0];
#pragma unroll
    for (int i = 1; i < 8; i++) bm = fmaxf(bm, red[i]);
    __syncthreads();
    float s = 0.f;
#pragma unroll
    for (int i = 0; i < 8; i++) { x[i] = expf(x[i] - bm); s += x[i]; }
#pragma unroll
    for (int o = 16; o; o >>= 1) s += __shfl_xor_sync(0xFFFFFFFFu, s, o);
    if (lane == 0) red[wid] = s;
    __syncthreads();
    float tot = red[0];
#pragma unroll
    for (int i = 1; i < 8; i++) tot += red[i];
    float inv = 1.0f / tot;
#pragma unroll
    for (int i = 0; i < 8; i++) {
        float a = x[i] * inv;
        __half h, l; split_f16(a, h, l);
        ah[t + i * 256] = h;
        al[t + i * 256] = l;
    }
}

// ---------------------- launch ----------------------------------------------
extern "C" void kernel_launch(void* const* d_in, const int* in_sizes, int n_in,
                              void* d_out, int out_size)
{
    const float* x  = (const float*)d_in[0];
    const float* Wq = (const float*)d_in[1];
    const float* Wk = (const float*)d_in[2];
    const float* Wv = (const float*)d_in[3];
    const float* P  = (const float*)d_in[4];
    const float* R  = (const float*)d_in[5];
    const float* tq = (const float*)d_in[6];
    const float* tk = (const float*)d_in[7];
    const float* tv = (const float*)d_in[8];
    float* out = (float*)d_out;

    cudaFuncSetAttribute(k_projQK, cudaFuncAttributeMaxDynamicSharedMemorySize, SMEMB);
    cudaFuncSetAttribute(k_projV,  cudaFuncAttributeMaxDynamicSharedMemorySize, SMEMB);
    cudaFuncSetAttribute(k_scores, cudaFuncAttributeMaxDynamicSharedMemorySize, SMEMB);
    cudaFuncSetAttribute(k_out,    cudaFuncAttributeMaxDynamicSharedMemorySize, SMEMB);

    conv_x<<<(MTOT * DDIM) / 1024, 256>>>(x);
    conv_wT<<<dim3(32, 32, 3), dim3(32, 8)>>>(Wq, Wk, Wv);
    bias_kernel<<<TWO_N, 256>>>(R);

    k_projQK<<<dim3(DDIM / 128, MTOT / 128, 2), 256, SMEMB>>>(tq, tk);
    k_projV <<<dim3(MTOT / 128, DDIM / 128, 1), 256, SMEMB>>>(tv);
    k_scores<<<dim3(NSEQ / 128, NSEQ / 128, BATCH), 256, SMEMB>>>(P);
    softmax_kernel<<<dim3(BATCH * NSEQ), 256>>>();
    k_out   <<<dim3(DDIM / 128, NSEQ / 128, BATCH), 256, SMEMB>>>(out);
}

// round 7
// speedup vs baseline: 4.4238x; 1.1289x over previous
#include <cuda_runtime.h>
#include <cuda_fp16.h>
#include <cstdint>

#define NSEQ 2048
#define DDIM 1024
#define BATCH 8
#define TWO_N (2*NSEQ)
#define MTOT (BATCH*NSEQ)          // 16384 flat rows

// ------------------------- scratch (__device__ globals) ---------------------
__device__ __half g_xh [(size_t)MTOT*DDIM];
__device__ __half g_xl [(size_t)MTOT*DDIM];
__device__ __half g_wth[3*(size_t)DDIM*DDIM];   // W^T hi, [which][dout][din]
__device__ __half g_wtl[3*(size_t)DDIM*DDIM];
__device__ __half g_qh [(size_t)MTOT*DDIM];      // q[n][d]
__device__ __half g_ql [(size_t)MTOT*DDIM];
__device__ __half g_kh [(size_t)MTOT*DDIM];      // k hi only (2-product scores)
__device__ __half g_vth[(size_t)BATCH*DDIM*NSEQ];// v^T hi only [b][e][m]
__device__ float  g_s  [(size_t)BATCH*NSEQ*NSEQ];// scores fp32
__device__ __half g_ah [(size_t)BATCH*NSEQ*NSEQ];// softmax hi/lo
__device__ __half g_al [(size_t)BATCH*NSEQ*NSEQ];
__device__ float  g_c  [TWO_N];

// ------------------------------ PTX helpers --------------------------------
__device__ __forceinline__ uint32_t smem_u32(const void* p) {
    uint32_t a;
    asm("{ .reg .u64 t; cvta.to.shared.u64 t, %1; cvt.u32.u64 %0, t; }" : "=r"(a) : "l"(p));
    return a;
}
__device__ __forceinline__ void cp_async16(uint32_t dst, const void* src) {
    asm volatile("cp.async.cg.shared.global [%0], [%1], 16;" :: "r"(dst), "l"(src));
}
#define CP_COMMIT() asm volatile("cp.async.commit_group;")

__device__ __forceinline__ void ldsm4(uint32_t (&r)[4], uint32_t addr) {
    asm volatile("ldmatrix.sync.aligned.m8n8.x4.shared.b16 {%0,%1,%2,%3}, [%4];"
        : "=r"(r[0]), "=r"(r[1]), "=r"(r[2]), "=r"(r[3]) : "r"(addr));
}
__device__ __forceinline__ void mma16816(float (&c)[4], const uint32_t (&a)[4],
                                         uint32_t b0, uint32_t b1) {
    asm volatile("mma.sync.aligned.m16n8k16.row.col.f32.f16.f16.f32 "
        "{%0,%1,%2,%3}, {%4,%5,%6,%7}, {%8,%9}, {%0,%1,%2,%3};"
        : "+f"(c[0]), "+f"(c[1]), "+f"(c[2]), "+f"(c[3])
        : "r"(a[0]), "r"(a[1]), "r"(a[2]), "r"(a[3]), "r"(b0), "r"(b1));
}

// ---------------------- split helpers --------------------------------------
__device__ __forceinline__ void split_f16(float v, __half& h, __half& l) {
    h = __float2half_rn(v);
    l = __float2half_rn(v - __half2float(h));
}

// ---------------------- GEMM core -------------------------------------------
// C[128 x 128] = sum over NP passes: Ap[p][rowTile..+128][:K] * Bp[p][colTile..+128][:K]^T
// A,B row-major fp16, row stride K. BK=64 (128B rows, XOR-swizzled), 3 stages.
// 8 warps, warp grid 4(M) x 2(N), warp tile 32x64 via 2x8 m16n8k16.
#define STAGES 3
#define TILEB  (128*128)              // 16384 B per tile
#define STAGEB (2*TILEB)              // 32768 B (A + B)
#define SMEMB  (STAGES*STAGEB)        // 98304 B

// physical smem offset for (row, 16B-seg) with bank swizzle
#define SWZ(row, seg) ((row) * 128 + ((((seg) ^ ((row) & 7))) << 4))

template<int NP>
__device__ __forceinline__ void gemm_mma(
    const __half* const* Ap, const __half* const* Bp,
    int K, size_t rowTile, size_t colTile, uint32_t sbase, float acc[2][8][4])
{
    const int tid  = threadIdx.x;
    const int lane = tid & 31;
    const int warp = tid >> 5;
    const int wm = warp & 3;          // M offset wm*32
    const int wn = warp >> 2;         // N offset wn*64
    const int KC  = K >> 6;           // 64-wide k chunks per pass
    const int NIT = NP * KC;

#pragma unroll
    for (int im = 0; im < 2; im++)
#pragma unroll
        for (int in = 0; in < 8; in++)
#pragma unroll
            for (int j = 0; j < 4; j++) acc[im][in][j] = 0.f;

    auto issue = [&](int j) {
        int p  = j / KC;
        int kb = (j % KC) << 6;
        const __half* A = Ap[p];
        const __half* B = Bp[p];
        uint32_t sA = sbase + (j % STAGES) * STAGEB;
        uint32_t sB = sA + TILEB;
#pragma unroll
        for (int i = 0; i < 4; i++) {
            int c = tid + 256 * i;            // 0..1023
            int row = c >> 3, seg = c & 7;
            cp_async16(sA + SWZ(row, seg),
                       A + (rowTile + row) * (size_t)K + kb + seg * 8);
        }
#pragma unroll
        for (int i = 0; i < 4; i++) {
            int c = tid + 256 * i;
            int row = c >> 3, seg = c & 7;
            cp_async16(sB + SWZ(row, seg),
                       B + (colTile + row) * (size_t)K + kb + seg * 8);
        }
        CP_COMMIT();
    };

    issue(0); issue(1);

    // ldmatrix lane decomposition (g = lane>>3)
    const uint32_t rm    = lane & 7;
    const uint32_t aRow0 = (uint32_t)(wm * 32 + ((lane >> 3) & 1) * 8 + rm) * 128;
    const uint32_t aColg = (uint32_t)(lane >> 4);          // g>>1
    const uint32_t bRow0 = (uint32_t)(wn * 64 + (lane >> 4) * 8 + rm) * 128;
    const uint32_t bColg = (uint32_t)((lane >> 3) & 1);    // g&1

    for (int it = 0; it < NIT; it++) {
        if (it + 1 < NIT) asm volatile("cp.async.wait_group 1;" ::: "memory");
        else              asm volatile("cp.async.wait_group 0;" ::: "memory");
        __syncthreads();
        if (it + 2 < NIT) issue(it + 2);

        uint32_t sA = sbase + (it % STAGES) * STAGEB;
        uint32_t sB = sA + TILEB;
#pragma unroll
        for (int ks = 0; ks < 4; ks++) {       // four k16 steps per 64-chunk
            uint32_t aC = (((uint32_t)(ks * 2) + aColg) ^ rm) << 4;
            uint32_t bC = (((uint32_t)(ks * 2) + bColg) ^ rm) << 4;
            uint32_t a0[4], a1[4], b[4][4];
            ldsm4(a0, sA + aRow0 + aC);
            ldsm4(a1, sA + aRow0 + 16 * 128 + aC);
#pragma unroll
            for (int inp = 0; inp < 4; inp++)
                ldsm4(b[inp], sB + bRow0 + inp * 16 * 128 + bC);
#pragma unroll
            for (int inp = 0; inp < 4; inp++) {
                mma16816(acc[0][inp * 2 + 0], a0, b[inp][0], b[inp][1]);
                mma16816(acc[1][inp * 2 + 0], a1, b[inp][0], b[inp][1]);
                mma16816(acc[0][inp * 2 + 1], a0, b[inp][2], b[inp][3]);
                mma16816(acc[1][inp * 2 + 1], a1, b[inp][2], b[inp][3]);
            }
        }
    }
}

// ---------------------- merged projection kernel ----------------------------
// z=0: q = tau_q * x·W_q (3-pass, store hi+lo at [n][d])
// z=1: k = tau_k * x·W_k_hi (2-pass, store hi at [n][d])
// z=2: v = tau_v * x·W_v_hi (2-pass, store hi transposed at [b][e][m])
__global__ __launch_bounds__(256, 2) void k_proj(const float* __restrict__ tq,
                                                 const float* __restrict__ tk,
                                                 const float* __restrict__ tv)
{
    extern __shared__ char dsm[];
    uint32_t sbase = smem_u32(dsm);
    int z = blockIdx.z;
    size_t woff = (size_t)z * DDIM * DDIM;
    float acc[2][8][4];
    int lane = threadIdx.x & 31, warp = threadIdx.x >> 5;
    int wm = warp & 3, wn = warp >> 2;

    if (z == 0) {
        size_t rowTile = (size_t)blockIdx.y * 128;   // flat n
        size_t colTile = (size_t)blockIdx.x * 128;   // d
        const __half* Ap[3] = { g_xh, g_xl, g_xh };
        const __half* Bp[3] = { g_wth, g_wth, g_wtl };
        gemm_mma<3>(Ap, Bp, DDIM, rowTile, colTile, sbase, acc);

        float tau = tq[0];
#pragma unroll
        for (int im = 0; im < 2; im++)
#pragma unroll
            for (int in = 0; in < 8; in++) {
                size_t n0 = rowTile + wm * 32 + im * 16 + (lane >> 2);
                size_t d  = colTile + wn * 64 + in * 8 + (lane & 3) * 2;
#pragma unroll
                for (int h = 0; h < 2; h++) {
                    size_t n = n0 + h * 8;
                    float v0 = acc[im][in][2 * h + 0] * tau;
                    float v1 = acc[im][in][2 * h + 1] * tau;
                    __half h0, l0, h1, l1;
                    split_f16(v0, h0, l0); split_f16(v1, h1, l1);
                    __half2 hv; hv.x = h0; hv.y = h1;
                    __half2 lv; lv.x = l0; lv.y = l1;
                    *(__half2*)&g_qh[n * DDIM + d] = hv;
                    *(__half2*)&g_ql[n * DDIM + d] = lv;
                }
            }
    } else if (z == 1) {
        size_t rowTile = (size_t)blockIdx.y * 128;   // flat n
        size_t colTile = (size_t)blockIdx.x * 128;   // d
        const __half* Ap[2] = { g_xh, g_xl };
        const __half* Bp[2] = { g_wth + woff, g_wth + woff };
        gemm_mma<2>(Ap, Bp, DDIM, rowTile, colTile, sbase, acc);

        float tau = tk[0];
#pragma unroll
        for (int im = 0; im < 2; im++)
#pragma unroll
            for (int in = 0; in < 8; in++) {
                size_t n0 = rowTile + wm * 32 + im * 16 + (lane >> 2);
                size_t d  = colTile + wn * 64 + in * 8 + (lane & 3) * 2;
#pragma unroll
                for (int h = 0; h < 2; h++) {
                    size_t n = n0 + h * 8;
                    __half2 hv;
                    hv.x = __float2half_rn(acc[im][in][2 * h + 0] * tau);
                    hv.y = __float2half_rn(acc[im][in][2 * h + 1] * tau);
                    *(__half2*)&g_kh[n * DDIM + d] = hv;
                }
            }
    } else {
        size_t rowTile = (size_t)blockIdx.x * 128;   // e (8 tiles)
        size_t colTile = (size_t)blockIdx.y * 128;   // flat n (128 tiles)
        const __half* Ap[2] = { g_wth + woff, g_wth + woff };
        const __half* Bp[2] = { g_xh, g_xl };
        gemm_mma<2>(Ap, Bp, DDIM, rowTile, colTile, sbase, acc);

        float tau = tv[0];
#pragma unroll
        for (int im = 0; im < 2; im++)
#pragma unroll
            for (int in = 0; in < 8; in++) {
                size_t e0 = rowTile + wm * 32 + im * 16 + (lane >> 2);
                size_t nf = colTile + wn * 64 + in * 8 + (lane & 3) * 2;
                size_t b = nf >> 11, m = nf & (NSEQ - 1);
#pragma unroll
                for (int h = 0; h < 2; h++) {
                    size_t e = e0 + h * 8;
                    __half2 hv;
                    hv.x = __float2half_rn(acc[im][in][2 * h + 0] * tau);
                    hv.y = __float2half_rn(acc[im][in][2 * h + 1] * tau);
                    *(__half2*)&g_vth[(b * DDIM + e) * NSEQ + m] = hv;
                }
            }
    }
}

// ---------------------- kernel: scores (2-product) --------------------------
// C[n][m] = q[n]·k[m];  S[b][n][m] = C*scale + P[n][m] + c[(n-m)&4095]
__global__ __launch_bounds__(256, 2) void k_scores(const float* __restrict__ P)
{
    extern __shared__ char dsm[];
    uint32_t sbase = smem_u32(dsm);
    int b = blockIdx.z;
    size_t rowTile = (size_t)b * NSEQ + blockIdx.y * 128;   // flat n into q
    size_t colTile = (size_t)b * NSEQ + blockIdx.x * 128;   // flat m into k

    const __half* Ap[2] = { g_qh, g_ql };
    const __half* Bp[2] = { g_kh, g_kh };
    float acc[2][8][4];
    gemm_mma<2>(Ap, Bp, DDIM, rowTile, colTile, sbase, acc);

    const float scale = 0.03125f;
    float* S = g_s + (size_t)b * NSEQ * NSEQ;
    int lane = threadIdx.x & 31, warp = threadIdx.x >> 5;
    int wm = warp & 3, wn = warp >> 2;
#pragma unroll
    for (int im = 0; im < 2; im++)
#pragma unroll
        for (int in = 0; in < 8; in++) {
            int n0 = blockIdx.y * 128 + wm * 32 + im * 16 + (lane >> 2);
            int m  = blockIdx.x * 128 + wn * 64 + in * 8 + (lane & 3) * 2;
#pragma unroll
            for (int h = 0; h < 2; h++) {
                int n = n0 + h * 8;
                float2 pv = *(const float2*)&P[(size_t)n * NSEQ + m];
                float2 v;
                v.x = acc[im][in][2 * h + 0] * scale + pv.x + g_c[(n - m) & (TWO_N - 1)];
                v.y = acc[im][in][2 * h + 1] * scale + pv.y + g_c[(n - m - 1) & (TWO_N - 1)];
                *(float2*)&S[(size_t)n * NSEQ + m] = v;
            }
        }
}

// ---------------------- kernel: out = A @ v (2-product) ---------------------
__global__ __launch_bounds__(256, 2) void k_out(float* __restrict__ O)
{
    extern __shared__ char dsm[];
    uint32_t sbase = smem_u32(dsm);
    int b = blockIdx.z;
    size_t rowTile = (size_t)b * NSEQ + blockIdx.y * 128;   // flat n into attn
    size_t colTile = (size_t)b * DDIM + blockIdx.x * 128;   // flat e into vT

    const __half* Ap[2] = { g_ah, g_al };
    const __half* Bp[2] = { g_vth, g_vth };
    float acc[2][8][4];
    gemm_mma<2>(Ap, Bp, NSEQ, rowTile, colTile, sbase, acc);

    int lane = threadIdx.x & 31, warp = threadIdx.x >> 5;
    int wm = warp & 3, wn = warp >> 2;
#pragma unroll
    for (int im = 0; im < 2; im++)
#pragma unroll
        for (int in = 0; in < 8; in++) {
            int n0 = blockIdx.y * 128 + wm * 32 + im * 16 + (lane >> 2);
            int e  = blockIdx.x * 128 + wn * 64 + in * 8 + (lane & 3) * 2;
#pragma unroll
            for (int h = 0; h < 2; h++) {
                int n = n0 + h * 8;
                float2 v = make_float2(acc[im][in][2 * h + 0], acc[im][in][2 * h + 1]);
                *(float2*)&O[((size_t)b * NSEQ + n) * DDIM + e] = v;
            }
        }
}

// ---------------------- conversion kernels ----------------------------------
__global__ __launch_bounds__(256) void conv_x(const float* __restrict__ x) {
    size_t i = (size_t)blockIdx.x * 256 + threadIdx.x;
    float4 v = ((const float4*)x)[i];
    __half h[4], l[4];
    split_f16(v.x, h[0], l[0]); split_f16(v.y, h[1], l[1]);
    split_f16(v.z, h[2], l[2]); split_f16(v.w, h[3], l[3]);
    size_t o = i * 4;
#pragma unroll
    for (int k = 0; k < 4; k++) { g_xh[o + k] = h[k]; g_xl[o + k] = l[k]; }
}

__global__ void conv_wT(const float* __restrict__ Wq, const float* __restrict__ Wk,
                        const float* __restrict__ Wv) {
    __shared__ float t[32][33];
    int z = blockIdx.z;
    const float* W = (z == 0) ? Wq : (z == 1) ? Wk : Wv;
    int bx = blockIdx.x * 32, by = blockIdx.y * 32;
    int tx = threadIdx.x, ty = threadIdx.y;       // block (32, 8)
#pragma unroll
    for (int i = 0; i < 4; i++)
        t[ty + i * 8][tx] = W[(size_t)(by + ty + i * 8) * DDIM + bx + tx];
    __syncthreads();
    size_t base = (size_t)z * DDIM * DDIM;
#pragma unroll
    for (int i = 0; i < 4; i++) {
        int d = bx + ty + i * 8, k = by + tx;
        float v = t[tx][ty + i * 8];
        __half h, l; split_f16(v, h, l);
        g_wth[base + (size_t)d * DDIM + k] = h;
        g_wtl[base + (size_t)d * DDIM + k] = l;
    }
}

// ---------------------- bias: c = real(ifft(R)) -----------------------------
__global__ __launch_bounds__(256) void bias_kernel(const float* __restrict__ R) {
    int t = blockIdx.x;
    int tid = threadIdx.x, lane = tid & 31, wid = tid >> 5;
    __shared__ float red[8];
    const float w = 6.283185307179586f / (float)TWO_N;
    float s = 0.f;
    for (int j = tid; j < TWO_N; j += 256)
        s += R[j] * cosf(w * (float)((j * t) & (TWO_N - 1)));
#pragma unroll
    for (int o = 16; o; o >>= 1) s += __shfl_xor_sync(0xFFFFFFFFu, s, o);
    if (lane == 0) red[wid] = s;
    __syncthreads();
    if (tid == 0) {
        float tot = 0.f;
#pragma unroll
        for (int i = 0; i < 8; i++) tot += red[i];
        g_c[t] = tot * (1.0f / (float)TWO_N);
    }
}

// ---------------------- softmax + fp16 split --------------------------------
__global__ __launch_bounds__(256) void softmax_kernel() {
    size_t row = blockIdx.x;
    float* p = g_s + row * NSEQ;
    __half* ah = g_ah + row * NSEQ;
    __half* al = g_al + row * NSEQ;
    int t = threadIdx.x, lane = t & 31, wid = t >> 5;
    __shared__ float red[8];

    float x[8];
#pragma unroll
    for (int i = 0; i < 8; i++) x[i] = p[t + i * 256];
    float m = x[0];
#pragma unroll
    for (int i = 1; i < 8; i++) m = fmaxf(m, x[i]);
#pragma unroll
    for (int o = 16; o; o >>= 1) m = fmaxf(m, __shfl_xor_sync(0xFFFFFFFFu, m, o));
    if (lane == 0) red[wid] = m;
    __syncthreads();
    float bm = red[0];
#pragma unroll
    for (int i = 1; i < 8; i++) bm = fmaxf(bm, red[i]);
    __syncthreads();
    float s = 0.f;
#pragma unroll
    for (int i = 0; i < 8; i++) { x[i] = expf(x[i] - bm); s += x[i]; }
#pragma unroll
    for (int o = 16; o; o >>= 1) s += __shfl_xor_sync(0xFFFFFFFFu, s, o);
    if (lane == 0) red[wid] = s;
    __syncthreads();
    float tot = red[0];
#pragma unroll
    for (int i = 1; i < 8; i++) tot += red[i];
    float inv = 1.0f / tot;
#pragma unroll
    for (int i = 0; i < 8; i++) {
        float a = x[i] * inv;
        __half h, l; split_f16(a, h, l);
        ah[t + i * 256] = h;
        al[t + i * 256] = l;
    }
}

// ---------------------- launch ----------------------------------------------
extern "C" void kernel_launch(void* const* d_in, const int* in_sizes, int n_in,
                              void* d_out, int out_size)
{
    const float* x  = (const float*)d_in[0];
    const float* Wq = (const float*)d_in[1];
    const float* Wk = (const float*)d_in[2];
    const float* Wv = (const float*)d_in[3];
    const float* P  = (const float*)d_in[4];
    const float* R  = (const float*)d_in[5];
    const float* tq = (const float*)d_in[6];
    const float* tk = (const float*)d_in[7];
    const float* tv = (const float*)d_in[8];
    float* out = (float*)d_out;

    cudaFuncSetAttribute(k_proj,   cudaFuncAttributeMaxDynamicSharedMemorySize, SMEMB);
    cudaFuncSetAttribute(k_scores, cudaFuncAttributeMaxDynamicSharedMemorySize, SMEMB);
    cudaFuncSetAttribute(k_out,    cudaFuncAttributeMaxDynamicSharedMemorySize, SMEMB);

    conv_x<<<(MTOT * DDIM) / 1024, 256>>>(x);
    conv_wT<<<dim3(32, 32, 3), dim3(32, 8)>>>(Wq, Wk, Wv);
    bias_kernel<<<TWO_N, 256>>>(R);

    k_proj  <<<dim3(DDIM / 128, MTOT / 128, 3), 256, SMEMB>>>(tq, tk, tv);
    k_scores<<<dim3(NSEQ / 128, NSEQ / 128, BATCH), 256, SMEMB>>>(P);
    softmax_kernel<<<dim3(BATCH * NSEQ), 256>>>();
    k_out   <<<dim3(DDIM / 128, NSEQ / 128, BATCH), 256, SMEMB>>>(out);
}

// round 10
// speedup vs baseline: 4.6491x; 1.0509x over previous
#include <cuda_runtime.h>
#include <cuda_fp16.h>
#include <cstdint>

#define NSEQ 2048
#define DDIM 1024
#define BATCH 8
#define TWO_N (2*NSEQ)
#define MTOT (BATCH*NSEQ)          // 16384 flat rows

// ------------------------- scratch (__device__ globals) ---------------------
__device__ __half g_xh [(size_t)MTOT*DDIM];
__device__ __half g_xl [(size_t)MTOT*DDIM];
__device__ __half g_wth[3*(size_t)DDIM*DDIM];   // W^T hi, [which][dout][din]
__device__ __half g_qh [(size_t)MTOT*DDIM];      // q[n][d]
__device__ __half g_ql [(size_t)MTOT*DDIM];
__device__ __half g_kh [(size_t)MTOT*DDIM];      // k hi only
__device__ __half g_vth[(size_t)BATCH*DDIM*NSEQ];// v^T hi only [b][e][m]
__device__ float  g_s  [(size_t)BATCH*NSEQ*NSEQ];// scores fp32
__device__ __half g_ah [(size_t)BATCH*NSEQ*NSEQ];// softmax hi/lo
__device__ __half g_al [(size_t)BATCH*NSEQ*NSEQ];
__device__ float  g_c  [TWO_N];

// ------------------------------ PTX helpers --------------------------------
__device__ __forceinline__ uint32_t smem_u32(const void* p) {
    uint32_t a;
    asm("{ .reg .u64 t; cvta.to.shared.u64 t, %1; cvt.u32.u64 %0, t; }" : "=r"(a) : "l"(p));
    return a;
}
__device__ __forceinline__ void cp_async16(uint32_t dst, const void* src) {
    asm volatile("cp.async.cg.shared.global [%0], [%1], 16;" :: "r"(dst), "l"(src));
}
#define CP_COMMIT() asm volatile("cp.async.commit_group;")

__device__ __forceinline__ void ldsm4(uint32_t (&r)[4], uint32_t addr) {
    asm volatile("ldmatrix.sync.aligned.m8n8.x4.shared.b16 {%0,%1,%2,%3}, [%4];"
        : "=r"(r[0]), "=r"(r[1]), "=r"(r[2]), "=r"(r[3]) : "r"(addr));
}
__device__ __forceinline__ void mma16816(float (&c)[4], const uint32_t (&a)[4],
                                         uint32_t b0, uint32_t b1) {
    asm volatile("mma.sync.aligned.m16n8k16.row.col.f32.f16.f16.f32 "
        "{%0,%1,%2,%3}, {%4,%5,%6,%7}, {%8,%9}, {%0,%1,%2,%3};"
        : "+f"(c[0]), "+f"(c[1]), "+f"(c[2]), "+f"(c[3])
        : "r"(a[0]), "r"(a[1]), "r"(a[2]), "r"(a[3]), "r"(b0), "r"(b1));
}

// ---------------------- split helpers --------------------------------------
__device__ __forceinline__ void split_f16(float v, __half& h, __half& l) {
    h = __float2half_rn(v);
    l = __float2half_rn(v - __half2float(h));
}

// ---------------------- GEMM core -------------------------------------------
// C[128 x 128] = sum over NP passes: Ap[p][rowTile..+128][:K] * Bp[p][colTile..+128][:K]^T
// A,B row-major fp16, row stride K. BK=64 (128B rows, XOR-swizzled), 3 stages.
// 8 warps, warp grid 4(M) x 2(N), warp tile 32x64 via 2x8 m16n8k16.
#define STAGES 3
#define TILEB  (128*128)              // 16384 B per tile
#define STAGEB (2*TILEB)              // 32768 B (A + B)
#define SMEMB  (STAGES*STAGEB)        // 98304 B

// physical smem offset for (row, 16B-seg) with bank swizzle
#define SWZ(row, seg) ((row) * 128 + ((((seg) ^ ((row) & 7))) << 4))

template<int NP>
__device__ __forceinline__ void gemm_mma(
    const __half* const* Ap, const __half* const* Bp,
    int K, size_t rowTile, size_t colTile, uint32_t sbase, float acc[2][8][4])
{
    const int tid  = threadIdx.x;
    const int lane = tid & 31;
    const int warp = tid >> 5;
    const int wm = warp & 3;          // M offset wm*32
    const int wn = warp >> 2;         // N offset wn*64
    const int KC  = K >> 6;           // 64-wide k chunks per pass
    const int NIT = NP * KC;

#pragma unroll
    for (int im = 0; im < 2; im++)
#pragma unroll
        for (int in = 0; in < 8; in++)
#pragma unroll
            for (int j = 0; j < 4; j++) acc[im][in][j] = 0.f;

    auto issue = [&](int j) {
        int p  = j / KC;
        int kb = (j % KC) << 6;
        const __half* A = Ap[p];
        const __half* B = Bp[p];
        uint32_t sA = sbase + (j % STAGES) * STAGEB;
        uint32_t sB = sA + TILEB;
#pragma unroll
        for (int i = 0; i < 4; i++) {
            int c = tid + 256 * i;            // 0..1023
            int row = c >> 3, seg = c & 7;
            cp_async16(sA + SWZ(row, seg),
                       A + (rowTile + row) * (size_t)K + kb + seg * 8);
        }
#pragma unroll
        for (int i = 0; i < 4; i++) {
            int c = tid + 256 * i;
            int row = c >> 3, seg = c & 7;
            cp_async16(sB + SWZ(row, seg),
                       B + (colTile + row) * (size_t)K + kb + seg * 8);
        }
        CP_COMMIT();
    };

    issue(0); issue(1);

    // ldmatrix lane decomposition (g = lane>>3)
    const uint32_t rm    = lane & 7;
    const uint32_t aRow0 = (uint32_t)(wm * 32 + ((lane >> 3) & 1) * 8 + rm) * 128;
    const uint32_t aColg = (uint32_t)(lane >> 4);          // g>>1
    const uint32_t bRow0 = (uint32_t)(wn * 64 + (lane >> 4) * 8 + rm) * 128;
    const uint32_t bColg = (uint32_t)((lane >> 3) & 1);    // g&1

    for (int it = 0; it < NIT; it++) {
        if (it + 1 < NIT) asm volatile("cp.async.wait_group 1;" ::: "memory");
        else              asm volatile("cp.async.wait_group 0;" ::: "memory");
        __syncthreads();
        if (it + 2 < NIT) issue(it + 2);

        uint32_t sA = sbase + (it % STAGES) * STAGEB;
        uint32_t sB = sA + TILEB;
#pragma unroll
        for (int ks = 0; ks < 4; ks++) {       // four k16 steps per 64-chunk
            uint32_t aC = (((uint32_t)(ks * 2) + aColg) ^ rm) << 4;
            uint32_t bC = (((uint32_t)(ks * 2) + bColg) ^ rm) << 4;
            uint32_t a0[4], a1[4], b[4][4];
            ldsm4(a0, sA + aRow0 + aC);
            ldsm4(a1, sA + aRow0 + 16 * 128 + aC);
#pragma unroll
            for (int inp = 0; inp < 4; inp++)
                ldsm4(b[inp], sB + bRow0 + inp * 16 * 128 + bC);
#pragma unroll
            for (int inp = 0; inp < 4; inp++) {
                mma16816(acc[0][inp * 2 + 0], a0, b[inp][0], b[inp][1]);
                mma16816(acc[1][inp * 2 + 0], a1, b[inp][0], b[inp][1]);
                mma16816(acc[0][inp * 2 + 1], a0, b[inp][2], b[inp][3]);
                mma16816(acc[1][inp * 2 + 1], a1, b[inp][2], b[inp][3]);
            }
        }
    }
}

// ---------------------- merged projection kernel (all 2-pass) ---------------
// z=0: q = tau_q * (x_h + x_l)·W_q_hi  (store hi+lo split at [n][d])
// z=1: k = tau_k * (x_h + x_l)·W_k_hi  (store hi at [n][d])
// z=2: v = tau_v * W_v_hi·(x_h + x_l)  (store hi transposed at [b][e][m])
__global__ __launch_bounds__(256, 2) void k_proj(const float* __restrict__ tq,
                                                 const float* __restrict__ tk,
                                                 const float* __restrict__ tv)
{
    extern __shared__ char dsm[];
    uint32_t sbase = smem_u32(dsm);
    int z = blockIdx.z;
    size_t woff = (size_t)z * DDIM * DDIM;
    float acc[2][8][4];
    int lane = threadIdx.x & 31, warp = threadIdx.x >> 5;
    int wm = warp & 3, wn = warp >> 2;

    if (z == 2) {
        size_t rowTile = (size_t)blockIdx.x * 128;   // e (8 tiles)
        size_t colTile = (size_t)blockIdx.y * 128;   // flat n (128 tiles)
        const __half* Ap[2] = { g_wth + woff, g_wth + woff };
        const __half* Bp[2] = { g_xh, g_xl };
        gemm_mma<2>(Ap, Bp, DDIM, rowTile, colTile, sbase, acc);

        float tau = tv[0];
#pragma unroll
        for (int im = 0; im < 2; im++)
#pragma unroll
            for (int in = 0; in < 8; in++) {
                size_t e0 = rowTile + wm * 32 + im * 16 + (lane >> 2);
                size_t nf = colTile + wn * 64 + in * 8 + (lane & 3) * 2;
                size_t b = nf >> 11, m = nf & (NSEQ - 1);
#pragma unroll
                for (int h = 0; h < 2; h++) {
                    size_t e = e0 + h * 8;
                    __half2 hv;
                    hv.x = __float2half_rn(acc[im][in][2 * h + 0] * tau);
                    hv.y = __float2half_rn(acc[im][in][2 * h + 1] * tau);
                    *(__half2*)&g_vth[(b * DDIM + e) * NSEQ + m] = hv;
                }
            }
    } else {
        size_t rowTile = (size_t)blockIdx.y * 128;   // flat n
        size_t colTile = (size_t)blockIdx.x * 128;   // d
        const __half* Ap[2] = { g_xh, g_xl };
        const __half* Bp[2] = { g_wth + woff, g_wth + woff };
        gemm_mma<2>(Ap, Bp, DDIM, rowTile, colTile, sbase, acc);

        float tau = z ? tk[0] : tq[0];
#pragma unroll
        for (int im = 0; im < 2; im++)
#pragma unroll
            for (int in = 0; in < 8; in++) {
                size_t n0 = rowTile + wm * 32 + im * 16 + (lane >> 2);
                size_t d  = colTile + wn * 64 + in * 8 + (lane & 3) * 2;
#pragma unroll
                for (int h = 0; h < 2; h++) {
                    size_t n = n0 + h * 8;
                    float v0 = acc[im][in][2 * h + 0] * tau;
                    float v1 = acc[im][in][2 * h + 1] * tau;
                    if (z == 0) {
                        __half h0, l0, h1, l1;
                        split_f16(v0, h0, l0); split_f16(v1, h1, l1);
                        __half2 hv; hv.x = h0; hv.y = h1;
                        __half2 lv; lv.x = l0; lv.y = l1;
                        *(__half2*)&g_qh[n * DDIM + d] = hv;
                        *(__half2*)&g_ql[n * DDIM + d] = lv;
                    } else {
                        __half2 hv;
                        hv.x = __float2half_rn(v0);
                        hv.y = __float2half_rn(v1);
                        *(__half2*)&g_kh[n * DDIM + d] = hv;
                    }
                }
            }
    }
}

// ---------------------- kernel: scores (2-product) --------------------------
// C[n][m] = q[n]·k[m];  S[b][n][m] = C*scale + P[n][m] + c[(n-m)&4095]
__global__ __launch_bounds__(256, 2) void k_scores(const float* __restrict__ P)
{
    extern __shared__ char dsm[];
    uint32_t sbase = smem_u32(dsm);
    int b = blockIdx.z;
    size_t rowTile = (size_t)b * NSEQ + blockIdx.y * 128;   // flat n into q
    size_t colTile = (size_t)b * NSEQ + blockIdx.x * 128;   // flat m into k

    const __half* Ap[2] = { g_qh, g_ql };
    const __half* Bp[2] = { g_kh, g_kh };
    float acc[2][8][4];
    gemm_mma<2>(Ap, Bp, DDIM, rowTile, colTile, sbase, acc);

    const float scale = 0.03125f;
    float* S = g_s + (size_t)b * NSEQ * NSEQ;
    int lane = threadIdx.x & 31, warp = threadIdx.x >> 5;
    int wm = warp & 3, wn = warp >> 2;
#pragma unroll
    for (int im = 0; im < 2; im++)
#pragma unroll
        for (int in = 0; in < 8; in++) {
            int n0 = blockIdx.y * 128 + wm * 32 + im * 16 + (lane >> 2);
            int m  = blockIdx.x * 128 + wn * 64 + in * 8 + (lane & 3) * 2;
#pragma unroll
            for (int h = 0; h < 2; h++) {
                int n = n0 + h * 8;
                float2 pv = *(const float2*)&P[(size_t)n * NSEQ + m];
                float2 v;
                v.x = acc[im][in][2 * h + 0] * scale + pv.x + g_c[(n - m) & (TWO_N - 1)];
                v.y = acc[im][in][2 * h + 1] * scale + pv.y + g_c[(n - m - 1) & (TWO_N - 1)];
                *(float2*)&S[(size_t)n * NSEQ + m] = v;
            }
        }
}

// ---------------------- kernel: out = A @ v (2-product) ---------------------
__global__ __launch_bounds__(256, 2) void k_out(float* __restrict__ O)
{
    extern __shared__ char dsm[];
    uint32_t sbase = smem_u32(dsm);
    int b = blockIdx.z;
    size_t rowTile = (size_t)b * NSEQ + blockIdx.y * 128;   // flat n into attn
    size_t colTile = (size_t)b * DDIM + blockIdx.x * 128;   // flat e into vT

    const __half* Ap[2] = { g_ah, g_al };
    const __half* Bp[2] = { g_vth, g_vth };
    float acc[2][8][4];
    gemm_mma<2>(Ap, Bp, NSEQ, rowTile, colTile, sbase, acc);

    int lane = threadIdx.x & 31, warp = threadIdx.x >> 5;
    int wm = warp & 3, wn = warp >> 2;
#pragma unroll
    for (int im = 0; im < 2; im++)
#pragma unroll
        for (int in = 0; in < 8; in++) {
            int n0 = blockIdx.y * 128 + wm * 32 + im * 16 + (lane >> 2);
            int e  = blockIdx.x * 128 + wn * 64 + in * 8 + (lane & 3) * 2;
#pragma unroll
            for (int h = 0; h < 2; h++) {
                int n = n0 + h * 8;
                float2 v = make_float2(acc[im][in][2 * h + 0], acc[im][in][2 * h + 1]);
                *(float2*)&O[((size_t)b * NSEQ + n) * DDIM + e] = v;
            }
        }
}

// ---------------------- merged prologue kernel ------------------------------
// blocks [0, NBX)            : x -> hi/lo split
// blocks [NBX, NBX+NBW)      : W transpose + split (hi only kept)
// blocks [NBX+NBW, +TWO_N)   : circulant bias column
#define NBX ((MTOT*DDIM)/1024)        // 16384
#define NBW (32*32*3)                 // 3072

__global__ __launch_bounds__(256) void k_prologue(
    const float* __restrict__ x,
    const float* __restrict__ Wq, const float* __restrict__ Wk,
    const float* __restrict__ Wv, const float* __restrict__ R)
{
    int blk = blockIdx.x;
    int tid = threadIdx.x;

    if (blk < NBX) {                         // ---- conv_x ----
        size_t i = (size_t)blk * 256 + tid;
        float4 v = ((const float4*)x)[i];
        __half h[4], l[4];
        split_f16(v.x, h[0], l[0]); split_f16(v.y, h[1], l[1]);
        split_f16(v.z, h[2], l[2]); split_f16(v.w, h[3], l[3]);
        size_t o = i * 4;
#pragma unroll
        for (int k = 0; k < 4; k++) { g_xh[o + k] = h[k]; g_xl[o + k] = l[k]; }
    } else if (blk < NBX + NBW) {            // ---- conv_wT ----
        int idx = blk - NBX;
        int z = idx / (32 * 32);
        int rem = idx % (32 * 32);
        const float* W = (z == 0) ? Wq : (z == 1) ? Wk : Wv;
        int bx = (rem % 32) * 32, by = (rem / 32) * 32;
        int tx = tid & 31, ty = tid >> 5;    // 32 x 8
        __shared__ float t[32][33];
#pragma unroll
        for (int i = 0; i < 4; i++)
            t[ty + i * 8][tx] = W[(size_t)(by + ty + i * 8) * DDIM + bx + tx];
        __syncthreads();
        size_t base = (size_t)z * DDIM * DDIM;
#pragma unroll
        for (int i = 0; i < 4; i++) {
            int d = bx + ty + i * 8, k = by + tx;
            g_wth[base + (size_t)d * DDIM + k] = __float2half_rn(t[tx][ty + i * 8]);
        }
    } else {                                 // ---- bias ----
        int t = blk - NBX - NBW;
        int lane = tid & 31, wid = tid >> 5;
        __shared__ float red[8];
        const float w = 6.283185307179586f / (float)TWO_N;
        float s = 0.f;
        for (int j = tid; j < TWO_N; j += 256)
            s += R[j] * cosf(w * (float)((j * t) & (TWO_N - 1)));
#pragma unroll
        for (int o = 16; o; o >>= 1) s += __shfl_xor_sync(0xFFFFFFFFu, s, o);
        if (lane == 0) red[wid] = s;
        __syncthreads();
        if (tid == 0) {
            float tot = 0.f;
#pragma unroll
            for (int i = 0; i < 8; i++) tot += red[i];
            g_c[t] = tot * (1.0f / (float)TWO_N);
        }
    }
}

// ---------------------- softmax + fp16 split --------------------------------
__global__ __launch_bounds__(256) void softmax_kernel() {
    size_t row = blockIdx.x;
    float* p = g_s + row * NSEQ;
    __half* ah = g_ah + row * NSEQ;
    __half* al = g_al + row * NSEQ;
    int t = threadIdx.x, lane = t & 31, wid = t >> 5;
    __shared__ float red[8];

    float x[8];
#pragma unroll
    for (int i = 0; i < 8; i++) x[i] = p[t + i * 256];
    float m = x[0];
#pragma unroll
    for (int i = 1; i < 8; i++) m = fmaxf(m, x[i]);
#pragma unroll
    for (int o = 16; o; o >>= 1) m = fmaxf(m, __shfl_xor_sync(0xFFFFFFFFu, m, o));
    if (lane == 0) red[wid] = m;
    __syncthreads();
    float bm = red[0];
#pragma unroll
    for (int i = 1; i < 8; i++) bm = fmaxf(bm, red[i]);
    __syncthreads();
    float s = 0.f;
#pragma unroll
    for (int i = 0; i < 8; i++) { x[i] = expf(x[i] - bm); s += x[i]; }
#pragma unroll
    for (int o = 16; o; o >>= 1) s += __shfl_xor_sync(0xFFFFFFFFu, s, o);
    if (lane == 0) red[wid] = s;
    __syncthreads();
    float tot = red[0];
#pragma unroll
    for (int i = 1; i < 8; i++) tot += red[i];
    float inv = 1.0f / tot;
#pragma unroll
    for (int i = 0; i < 8; i++) {
        float a = x[i] * inv;
        __half h, l; split_f16(a, h, l);
        ah[t + i * 256] = h;
        al[t + i * 256] = l;
    }
}

// ---------------------- launch ----------------------------------------------
extern "C" void kernel_launch(void* const* d_in, const int* in_sizes, int n_in,
                              void* d_out, int out_size)
{
    const float* x  = (const float*)d_in[0];
    const float* Wq = (const float*)d_in[1];
    const float* Wk = (const float*)d_in[2];
    const float* Wv = (const float*)d_in[3];
    const float* P  = (const float*)d_in[4];
    const float* R  = (const float*)d_in[5];
    const float* tq = (const float*)d_in[6];
    const float* tk = (const float*)d_in[7];
    const float* tv = (const float*)d_in[8];
    float* out = (float*)d_out;

    cudaFuncSetAttribute(k_proj,   cudaFuncAttributeMaxDynamicSharedMemorySize, SMEMB);
    cudaFuncSetAttribute(k_scores, cudaFuncAttributeMaxDynamicSharedMemorySize, SMEMB);
    cudaFuncSetAttribute(k_out,    cudaFuncAttributeMaxDynamicSharedMemorySize, SMEMB);

    k_prologue<<<NBX + NBW + TWO_N, 256>>>(x, Wq, Wk, Wv, R);
    k_proj  <<<dim3(DDIM / 128, MTOT / 128, 3), 256, SMEMB>>>(tq, tk, tv);
    k_scores<<<dim3(NSEQ / 128, NSEQ / 128, BATCH), 256, SMEMB>>>(P);
    softmax_kernel<<<dim3(BATCH * NSEQ), 256>>>();
    k_out   <<<dim3(DDIM / 128, NSEQ / 128, BATCH), 256, SMEMB>>>(out);
}

// round 12
// speedup vs baseline: 6.3424x; 1.3642x over previous
#include <cuda_runtime.h>
#include <cuda_fp16.h>
#include <cstdint>

#define NSEQ 2048
#define DDIM 1024
#define BATCH 8
#define TWO_N (2*NSEQ)
#define MTOT (BATCH*NSEQ)          // 16384 flat rows

// ------------------------- scratch (__device__ globals) ---------------------
__device__ __half g_xh [(size_t)MTOT*DDIM];
__device__ __half g_xl [(size_t)MTOT*DDIM];
__device__ __half g_wth[3*(size_t)DDIM*DDIM];   // W^T hi, [which][dout][din]
__device__ __half g_qh [(size_t)MTOT*DDIM];      // q hi only
__device__ __half g_kh [(size_t)MTOT*DDIM];      // k hi only
__device__ __half g_vth[(size_t)BATCH*DDIM*NSEQ];// v^T hi only [b][e][m]
__device__ float  g_s  [(size_t)BATCH*NSEQ*NSEQ];// scores fp32
__device__ __half g_ah [(size_t)BATCH*NSEQ*NSEQ];// softmax hi only
__device__ float  g_c  [TWO_N];

// ------------------------------ PTX helpers --------------------------------
__device__ __forceinline__ uint32_t smem_u32(const void* p) {
    uint32_t a;
    asm("{ .reg .u64 t; cvta.to.shared.u64 t, %1; cvt.u32.u64 %0, t; }" : "=r"(a) : "l"(p));
    return a;
}
__device__ __forceinline__ void cp_async16(uint32_t dst, const void* src) {
    asm volatile("cp.async.cg.shared.global [%0], [%1], 16;" :: "r"(dst), "l"(src));
}
#define CP_COMMIT() asm volatile("cp.async.commit_group;")

__device__ __forceinline__ void ldsm4(uint32_t (&r)[4], uint32_t addr) {
    asm volatile("ldmatrix.sync.aligned.m8n8.x4.shared.b16 {%0,%1,%2,%3}, [%4];"
        : "=r"(r[0]), "=r"(r[1]), "=r"(r[2]), "=r"(r[3]) : "r"(addr));
}
__device__ __forceinline__ void mma16816(float (&c)[4], const uint32_t (&a)[4],
                                         uint32_t b0, uint32_t b1) {
    asm volatile("mma.sync.aligned.m16n8k16.row.col.f32.f16.f16.f32 "
        "{%0,%1,%2,%3}, {%4,%5,%6,%7}, {%8,%9}, {%0,%1,%2,%3};"
        : "+f"(c[0]), "+f"(c[1]), "+f"(c[2]), "+f"(c[3])
        : "r"(a[0]), "r"(a[1]), "r"(a[2]), "r"(a[3]), "r"(b0), "r"(b1));
}

// ---------------------- split helpers --------------------------------------
__device__ __forceinline__ void split_f16(float v, __half& h, __half& l) {
    h = __float2half_rn(v);
    l = __float2half_rn(v - __half2float(h));
}

// ---------------------- GEMM core -------------------------------------------
// C[128 x 128] = sum over NP passes: Ap[p][rowTile..+128][:K] * Bp[p][colTile..+128][:K]^T
// A,B row-major fp16, row stride K. BK=64 (128B rows, XOR-swizzled), 3 stages.
// 8 warps, warp grid 4(M) x 2(N), warp tile 32x64 via 2x8 m16n8k16.
#define STAGES 3
#define TILEB  (128*128)              // 16384 B per tile
#define STAGEB (2*TILEB)              // 32768 B (A + B)
#define SMEMB  (STAGES*STAGEB)        // 98304 B

// physical smem offset for (row, 16B-seg) with bank swizzle
#define SWZ(row, seg) ((row) * 128 + ((((seg) ^ ((row) & 7))) << 4))

template<int NP>
__device__ __forceinline__ void gemm_mma(
    const __half* const* Ap, const __half* const* Bp,
    int K, size_t rowTile, size_t colTile, uint32_t sbase, float acc[2][8][4])
{
    const int tid  = threadIdx.x;
    const int lane = tid & 31;
    const int warp = tid >> 5;
    const int wm = warp & 3;          // M offset wm*32
    const int wn = warp >> 2;         // N offset wn*64
    const int KC  = K >> 6;           // 64-wide k chunks per pass
    const int NIT = NP * KC;

#pragma unroll
    for (int im = 0; im < 2; im++)
#pragma unroll
        for (int in = 0; in < 8; in++)
#pragma unroll
            for (int j = 0; j < 4; j++) acc[im][in][j] = 0.f;

    auto issue = [&](int j) {
        int p  = j / KC;
        int kb = (j % KC) << 6;
        const __half* A = Ap[p];
        const __half* B = Bp[p];
        uint32_t sA = sbase + (j % STAGES) * STAGEB;
        uint32_t sB = sA + TILEB;
#pragma unroll
        for (int i = 0; i < 4; i++) {
            int c = tid + 256 * i;            // 0..1023
            int row = c >> 3, seg = c & 7;
            cp_async16(sA + SWZ(row, seg),
                       A + (rowTile + row) * (size_t)K + kb + seg * 8);
        }
#pragma unroll
        for (int i = 0; i < 4; i++) {
            int c = tid + 256 * i;
            int row = c >> 3, seg = c & 7;
            cp_async16(sB + SWZ(row, seg),
                       B + (colTile + row) * (size_t)K + kb + seg * 8);
        }
        CP_COMMIT();
    };

    issue(0); issue(1);

    // ldmatrix lane decomposition (g = lane>>3)
    const uint32_t rm    = lane & 7;
    const uint32_t aRow0 = (uint32_t)(wm * 32 + ((lane >> 3) & 1) * 8 + rm) * 128;
    const uint32_t aColg = (uint32_t)(lane >> 4);          // g>>1
    const uint32_t bRow0 = (uint32_t)(wn * 64 + (lane >> 4) * 8 + rm) * 128;
    const uint32_t bColg = (uint32_t)((lane >> 3) & 1);    // g&1

    for (int it = 0; it < NIT; it++) {
        if (it + 1 < NIT) asm volatile("cp.async.wait_group 1;" ::: "memory");
        else              asm volatile("cp.async.wait_group 0;" ::: "memory");
        __syncthreads();
        if (it + 2 < NIT) issue(it + 2);

        uint32_t sA = sbase + (it % STAGES) * STAGEB;
        uint32_t sB = sA + TILEB;
#pragma unroll
        for (int ks = 0; ks < 4; ks++) {       // four k16 steps per 64-chunk
            uint32_t aC = (((uint32_t)(ks * 2) + aColg) ^ rm) << 4;
            uint32_t bC = (((uint32_t)(ks * 2) + bColg) ^ rm) << 4;
            uint32_t a0[4], a1[4], b[4][4];
            ldsm4(a0, sA + aRow0 + aC);
            ldsm4(a1, sA + aRow0 + 16 * 128 + aC);
#pragma unroll
            for (int inp = 0; inp < 4; inp++)
                ldsm4(b[inp], sB + bRow0 + inp * 16 * 128 + bC);
#pragma unroll
            for (int inp = 0; inp < 4; inp++) {
                mma16816(acc[0][inp * 2 + 0], a0, b[inp][0], b[inp][1]);
                mma16816(acc[1][inp * 2 + 0], a1, b[inp][0], b[inp][1]);
                mma16816(acc[0][inp * 2 + 1], a0, b[inp][2], b[inp][3]);
                mma16816(acc[1][inp * 2 + 1], a1, b[inp][2], b[inp][3]);
            }
        }
    }
}

// ---------------------- merged projection kernel (all 2-pass, hi-only out) --
// z=0: q = tau_q * (x_h + x_l)·W_q_hi  (store hi at [n][d])
// z=1: k = tau_k * (x_h + x_l)·W_k_hi  (store hi at [n][d])
// z=2: v = tau_v * W_v_hi·(x_h + x_l)  (store hi transposed at [b][e][m])
__global__ __launch_bounds__(256, 2) void k_proj(const float* __restrict__ tq,
                                                 const float* __restrict__ tk,
                                                 const float* __restrict__ tv)
{
    extern __shared__ char dsm[];
    uint32_t sbase = smem_u32(dsm);
    int z = blockIdx.z;
    size_t woff = (size_t)z * DDIM * DDIM;
    float acc[2][8][4];
    int lane = threadIdx.x & 31, warp = threadIdx.x >> 5;
    int wm = warp & 3, wn = warp >> 2;

    if (z == 2) {
        size_t rowTile = (size_t)blockIdx.x * 128;   // e (8 tiles)
        size_t colTile = (size_t)blockIdx.y * 128;   // flat n (128 tiles)
        const __half* Ap[2] = { g_wth + woff, g_wth + woff };
        const __half* Bp[2] = { g_xh, g_xl };
        gemm_mma<2>(Ap, Bp, DDIM, rowTile, colTile, sbase, acc);

        float tau = tv[0];
#pragma unroll
        for (int im = 0; im < 2; im++)
#pragma unroll
            for (int in = 0; in < 8; in++) {
                size_t e0 = rowTile + wm * 32 + im * 16 + (lane >> 2);
                size_t nf = colTile + wn * 64 + in * 8 + (lane & 3) * 2;
                size_t b = nf >> 11, m = nf & (NSEQ - 1);
#pragma unroll
                for (int h = 0; h < 2; h++) {
                    size_t e = e0 + h * 8;
                    __half2 hv;
                    hv.x = __float2half_rn(acc[im][in][2 * h + 0] * tau);
                    hv.y = __float2half_rn(acc[im][in][2 * h + 1] * tau);
                    *(__half2*)&g_vth[(b * DDIM + e) * NSEQ + m] = hv;
                }
            }
    } else {
        size_t rowTile = (size_t)blockIdx.y * 128;   // flat n
        size_t colTile = (size_t)blockIdx.x * 128;   // d
        const __half* Ap[2] = { g_xh, g_xl };
        const __half* Bp[2] = { g_wth + woff, g_wth + woff };
        gemm_mma<2>(Ap, Bp, DDIM, rowTile, colTile, sbase, acc);

        float tau = z ? tk[0] : tq[0];
        __half* O = z ? g_kh : g_qh;
#pragma unroll
        for (int im = 0; im < 2; im++)
#pragma unroll
            for (int in = 0; in < 8; in++) {
                size_t n0 = rowTile + wm * 32 + im * 16 + (lane >> 2);
                size_t d  = colTile + wn * 64 + in * 8 + (lane & 3) * 2;
#pragma unroll
                for (int h = 0; h < 2; h++) {
                    size_t n = n0 + h * 8;
                    __half2 hv;
                    hv.x = __float2half_rn(acc[im][in][2 * h + 0] * tau);
                    hv.y = __float2half_rn(acc[im][in][2 * h + 1] * tau);
                    *(__half2*)&O[n * DDIM + d] = hv;
                }
            }
    }
}

// ---------------------- kernel: scores (1-pass) -----------------------------
// C[n][m] = q_h[n]·k_h[m];  S[b][n][m] = C*scale + P[n][m] + c[(n-m)&4095]
__global__ __launch_bounds__(256, 2) void k_scores(const float* __restrict__ P)
{
    extern __shared__ char dsm[];
    uint32_t sbase = smem_u32(dsm);
    int b = blockIdx.z;
    size_t rowTile = (size_t)b * NSEQ + blockIdx.y * 128;   // flat n into q
    size_t colTile = (size_t)b * NSEQ + blockIdx.x * 128;   // flat m into k

    const __half* Ap[1] = { g_qh };
    const __half* Bp[1] = { g_kh };
    float acc[2][8][4];
    gemm_mma<1>(Ap, Bp, DDIM, rowTile, colTile, sbase, acc);

    const float scale = 0.03125f;
    float* S = g_s + (size_t)b * NSEQ * NSEQ;
    int lane = threadIdx.x & 31, warp = threadIdx.x >> 5;
    int wm = warp & 3, wn = warp >> 2;
#pragma unroll
    for (int im = 0; im < 2; im++)
#pragma unroll
        for (int in = 0; in < 8; in++) {
            int n0 = blockIdx.y * 128 + wm * 32 + im * 16 + (lane >> 2);
            int m  = blockIdx.x * 128 + wn * 64 + in * 8 + (lane & 3) * 2;
#pragma unroll
            for (int h = 0; h < 2; h++) {
                int n = n0 + h * 8;
                float2 pv = *(const float2*)&P[(size_t)n * NSEQ + m];
                float2 v;
                v.x = acc[im][in][2 * h + 0] * scale + pv.x + g_c[(n - m) & (TWO_N - 1)];
                v.y = acc[im][in][2 * h + 1] * scale + pv.y + g_c[(n - m - 1) & (TWO_N - 1)];
                *(float2*)&S[(size_t)n * NSEQ + m] = v;
            }
        }
}

// ---------------------- kernel: out = A_h @ v_h (1-pass) --------------------
__global__ __launch_bounds__(256, 2) void k_out(float* __restrict__ O)
{
    extern __shared__ char dsm[];
    uint32_t sbase = smem_u32(dsm);
    int b = blockIdx.z;
    size_t rowTile = (size_t)b * NSEQ + blockIdx.y * 128;   // flat n into attn
    size_t colTile = (size_t)b * DDIM + blockIdx.x * 128;   // flat e into vT

    const __half* Ap[1] = { g_ah };
    const __half* Bp[1] = { g_vth };
    float acc[2][8][4];
    gemm_mma<1>(Ap, Bp, NSEQ, rowTile, colTile, sbase, acc);

    int lane = threadIdx.x & 31, warp = threadIdx.x >> 5;
    int wm = warp & 3, wn = warp >> 2;
#pragma unroll
    for (int im = 0; im < 2; im++)
#pragma unroll
        for (int in = 0; in < 8; in++) {
            int n0 = blockIdx.y * 128 + wm * 32 + im * 16 + (lane >> 2);
            int e  = blockIdx.x * 128 + wn * 64 + in * 8 + (lane & 3) * 2;
#pragma unroll
            for (int h = 0; h < 2; h++) {
                int n = n0 + h * 8;
                float2 v = make_float2(acc[im][in][2 * h + 0], acc[im][in][2 * h + 1]);
                *(float2*)&O[((size_t)b * NSEQ + n) * DDIM + e] = v;
            }
        }
}

// ---------------------- merged prologue kernel ------------------------------
// blocks [0, NBX)            : x -> hi/lo split
// blocks [NBX, NBX+NBW)      : W transpose (hi only)
// blocks [NBX+NBW, +TWO_N)   : circulant bias column
#define NBX ((MTOT*DDIM)/1024)        // 16384
#define NBW (32*32*3)                 // 3072

__global__ __launch_bounds__(256) void k_prologue(
    const float* __restrict__ x,
    const float* __restrict__ Wq, const float* __restrict__ Wk,
    const float* __restrict__ Wv, const float* __restrict__ R)
{
    int blk = blockIdx.x;
    int tid = threadIdx.x;

    if (blk < NBX) {                         // ---- conv_x ----
        size_t i = (size_t)blk * 256 + tid;
        float4 v = ((const float4*)x)[i];
        __half h[4], l[4];
        split_f16(v.x, h[0], l[0]); split_f16(v.y, h[1], l[1]);
        split_f16(v.z, h[2], l[2]); split_f16(v.w, h[3], l[3]);
        size_t o = i * 4;
#pragma unroll
        for (int k = 0; k < 4; k++) { g_xh[o + k] = h[k]; g_xl[o + k] = l[k]; }
    } else if (blk < NBX + NBW) {            // ---- conv_wT ----
        int idx = blk - NBX;
        int z = idx / (32 * 32);
        int rem = idx % (32 * 32);
        const float* W = (z == 0) ? Wq : (z == 1) ? Wk : Wv;
        int bx = (rem % 32) * 32, by = (rem / 32) * 32;
        int tx = tid & 31, ty = tid >> 5;    // 32 x 8
        __shared__ float t[32][33];
#pragma unroll
        for (int i = 0; i < 4; i++)
            t[ty + i * 8][tx] = W[(size_t)(by + ty + i * 8) * DDIM + bx + tx];
        __syncthreads();
        size_t base = (size_t)z * DDIM * DDIM;
#pragma unroll
        for (int i = 0; i < 4; i++) {
            int d = bx + ty + i * 8, k = by + tx;
            g_wth[base + (size_t)d * DDIM + k] = __float2half_rn(t[tx][ty + i * 8]);
        }
    } else {                                 // ---- bias ----
        int t = blk - NBX - NBW;
        int lane = tid & 31, wid = tid >> 5;
        __shared__ float red[8];
        const float w = 6.283185307179586f / (float)TWO_N;
        float s = 0.f;
        for (int j = tid; j < TWO_N; j += 256)
            s += R[j] * cosf(w * (float)((j * t) & (TWO_N - 1)));
#pragma unroll
        for (int o = 16; o; o >>= 1) s += __shfl_xor_sync(0xFFFFFFFFu, s, o);
        if (lane == 0) red[wid] = s;
        __syncthreads();
        if (tid == 0) {
            float tot = 0.f;
#pragma unroll
            for (int i = 0; i < 8; i++) tot += red[i];
            g_c[t] = tot * (1.0f / (float)TWO_N);
        }
    }
}

// ---------------------- softmax (hi-only store) -----------------------------
__global__ __launch_bounds__(256) void softmax_kernel() {
    size_t row = blockIdx.x;
    float* p = g_s + row * NSEQ;
    __half* ah = g_ah + row * NSEQ;
    int t = threadIdx.x, lane = t & 31, wid = t >> 5;
    __shared__ float red[8];

    float x[8];
#pragma unroll
    for (int i = 0; i < 8; i++) x[i] = p[t + i * 256];
    float m = x[0];
#pragma unroll
    for (int i = 1; i < 8; i++) m = fmaxf(m, x[i]);
#pragma unroll
    for (int o = 16; o; o >>= 1) m = fmaxf(m, __shfl_xor_sync(0xFFFFFFFFu, m, o));
    if (lane == 0) red[wid] = m;
    __syncthreads();
    float bm = red[0];
#pragma unroll
    for (int i = 1; i < 8; i++) bm = fmaxf(bm, red[i]);
    __syncthreads();
    float s = 0.f;
#pragma unroll
    for (int i = 0; i < 8; i++) { x[i] = expf(x[i] - bm); s += x[i]; }
#pragma unroll
    for (int o = 16; o; o >>= 1) s += __shfl_xor_sync(0xFFFFFFFFu, s, o);
    if (lane == 0) red[wid] = s;
    __syncthreads();
    float tot = red[0];
#pragma unroll
    for (int i = 1; i < 8; i++) tot += red[i];
    float inv = 1.0f / tot;
#pragma unroll
    for (int i = 0; i < 8; i++)
        ah[t + i * 256] = __float2half_rn(x[i] * inv);
}

// ---------------------- launch ----------------------------------------------
extern "C" void kernel_launch(void* const* d_in, const int* in_sizes, int n_in,
                              void* d_out, int out_size)
{
    const float* x  = (const float*)d_in[0];
    const float* Wq = (const float*)d_in[1];
    const float* Wk = (const float*)d_in[2];
    const float* Wv = (const float*)d_in[3];
    const float* P  = (const float*)d_in[4];
    const float* R  = (const float*)d_in[5];
    const float* tq = (const float*)d_in[6];
    const float* tk = (const float*)d_in[7];
    const float* tv = (const float*)d_in[8];
    float* out = (float*)d_out;

    cudaFuncSetAttribute(k_proj,   cudaFuncAttributeMaxDynamicSharedMemorySize, SMEMB);
    cudaFuncSetAttribute(k_scores, cudaFuncAttributeMaxDynamicSharedMemorySize, SMEMB);
    cudaFuncSetAttribute(k_out,    cudaFuncAttributeMaxDynamicSharedMemorySize, SMEMB);

    k_prologue<<<NBX + NBW + TWO_N, 256>>>(x, Wq, Wk, Wv, R);
    k_proj  <<<dim3(DDIM / 128, MTOT / 128, 3), 256, SMEMB>>>(tq, tk, tv);
    k_scores<<<dim3(NSEQ / 128, NSEQ / 128, BATCH), 256, SMEMB>>>(P);
    softmax_kernel<<<dim3(BATCH * NSEQ), 256>>>();
    k_out   <<<dim3(DDIM / 128, NSEQ / 128, BATCH), 256, SMEMB>>>(out);
}

// round 14
// speedup vs baseline: 8.6532x; 1.3643x over previous
#include <cuda_runtime.h>
#include <cuda_fp16.h>
#include <cstdint>

#define NSEQ 2048
#define DDIM 1024
#define BATCH 8
#define TWO_N (2*NSEQ)
#define MTOT (BATCH*NSEQ)          // 16384 flat rows

// ------------------------- scratch (__device__ globals) ---------------------
__device__ __half g_xh [(size_t)MTOT*DDIM];
__device__ __half g_wth[3*(size_t)DDIM*DDIM];   // W^T hi, [which][dout][din]
__device__ __half g_qh [(size_t)MTOT*DDIM];      // q hi only
__device__ __half g_kh [(size_t)MTOT*DDIM];      // k hi only
__device__ __half g_vth[(size_t)BATCH*DDIM*NSEQ];// v^T hi only [b][e][m]
__device__ float  g_s  [(size_t)BATCH*NSEQ*NSEQ];// scores fp32
__device__ __half g_ah [(size_t)BATCH*NSEQ*NSEQ];// softmax hi only
__device__ float  g_c  [TWO_N];

// ------------------------------ PTX helpers --------------------------------
__device__ __forceinline__ uint32_t smem_u32(const void* p) {
    uint32_t a;
    asm("{ .reg .u64 t; cvta.to.shared.u64 t, %1; cvt.u32.u64 %0, t; }" : "=r"(a) : "l"(p));
    return a;
}
__device__ __forceinline__ void cp_async16(uint32_t dst, const void* src) {
    asm volatile("cp.async.cg.shared.global [%0], [%1], 16;" :: "r"(dst), "l"(src));
}
#define CP_COMMIT() asm volatile("cp.async.commit_group;")

__device__ __forceinline__ void ldsm4(uint32_t (&r)[4], uint32_t addr) {
    asm volatile("ldmatrix.sync.aligned.m8n8.x4.shared.b16 {%0,%1,%2,%3}, [%4];"
        : "=r"(r[0]), "=r"(r[1]), "=r"(r[2]), "=r"(r[3]) : "r"(addr));
}
__device__ __forceinline__ void mma16816(float (&c)[4], const uint32_t (&a)[4],
                                         uint32_t b0, uint32_t b1) {
    asm volatile("mma.sync.aligned.m16n8k16.row.col.f32.f16.f16.f32 "
        "{%0,%1,%2,%3}, {%4,%5,%6,%7}, {%8,%9}, {%0,%1,%2,%3};"
        : "+f"(c[0]), "+f"(c[1]), "+f"(c[2]), "+f"(c[3])
        : "r"(a[0]), "r"(a[1]), "r"(a[2]), "r"(a[3]), "r"(b0), "r"(b1));
}

// ---------------------- GEMM core -------------------------------------------
// C[128 x 128] = sum over NP passes: Ap[p][rowTile..+128][:K] * Bp[p][colTile..+128][:K]^T
// A,B row-major fp16, row stride K. BK=64 (128B rows, XOR-swizzled), 3 stages.
// 8 warps, warp grid 4(M) x 2(N), warp tile 32x64 via 2x8 m16n8k16.
#define STAGES 3
#define TILEB  (128*128)              // 16384 B per tile
#define STAGEB (2*TILEB)              // 32768 B (A + B)
#define SMEMB  (STAGES*STAGEB)        // 98304 B

// physical smem offset for (row, 16B-seg) with bank swizzle
#define SWZ(row, seg) ((row) * 128 + ((((seg) ^ ((row) & 7))) << 4))

template<int NP>
__device__ __forceinline__ void gemm_mma(
    const __half* const* Ap, const __half* const* Bp,
    int K, size_t rowTile, size_t colTile, uint32_t sbase, float acc[2][8][4])
{
    const int tid  = threadIdx.x;
    const int lane = tid & 31;
    const int warp = tid >> 5;
    const int wm = warp & 3;          // M offset wm*32
    const int wn = warp >> 2;         // N offset wn*64
    const int KC  = K >> 6;           // 64-wide k chunks per pass
    const int NIT = NP * KC;

#pragma unroll
    for (int im = 0; im < 2; im++)
#pragma unroll
        for (int in = 0; in < 8; in++)
#pragma unroll
            for (int j = 0; j < 4; j++) acc[im][in][j] = 0.f;

    auto issue = [&](int j) {
        int p  = j / KC;
        int kb = (j % KC) << 6;
        const __half* A = Ap[p];
        const __half* B = Bp[p];
        uint32_t sA = sbase + (j % STAGES) * STAGEB;
        uint32_t sB = sA + TILEB;
#pragma unroll
        for (int i = 0; i < 4; i++) {
            int c = tid + 256 * i;            // 0..1023
            int row = c >> 3, seg = c & 7;
            cp_async16(sA + SWZ(row, seg),
                       A + (rowTile + row) * (size_t)K + kb + seg * 8);
        }
#pragma unroll
        for (int i = 0; i < 4; i++) {
            int c = tid + 256 * i;
            int row = c >> 3, seg = c & 7;
            cp_async16(sB + SWZ(row, seg),
                       B + (colTile + row) * (size_t)K + kb + seg * 8);
        }
        CP_COMMIT();
    };

    issue(0); issue(1);

    // ldmatrix lane decomposition (g = lane>>3)
    const uint32_t rm    = lane & 7;
    const uint32_t aRow0 = (uint32_t)(wm * 32 + ((lane >> 3) & 1) * 8 + rm) * 128;
    const uint32_t aColg = (uint32_t)(lane >> 4);          // g>>1
    const uint32_t bRow0 = (uint32_t)(wn * 64 + (lane >> 4) * 8 + rm) * 128;
    const uint32_t bColg = (uint32_t)((lane >> 3) & 1);    // g&1

    for (int it = 0; it < NIT; it++) {
        if (it + 1 < NIT) asm volatile("cp.async.wait_group 1;" ::: "memory");
        else              asm volatile("cp.async.wait_group 0;" ::: "memory");
        __syncthreads();
        if (it + 2 < NIT) issue(it + 2);

        uint32_t sA = sbase + (it % STAGES) * STAGEB;
        uint32_t sB = sA + TILEB;
#pragma unroll
        for (int ks = 0; ks < 4; ks++) {       // four k16 steps per 64-chunk
            uint32_t aC = (((uint32_t)(ks * 2) + aColg) ^ rm) << 4;
            uint32_t bC = (((uint32_t)(ks * 2) + bColg) ^ rm) << 4;
            uint32_t a0[4], a1[4], b[4][4];
            ldsm4(a0, sA + aRow0 + aC);
            ldsm4(a1, sA + aRow0 + 16 * 128 + aC);
#pragma unroll
            for (int inp = 0; inp < 4; inp++)
                ldsm4(b[inp], sB + bRow0 + inp * 16 * 128 + bC);
#pragma unroll
            for (int inp = 0; inp < 4; inp++) {
                mma16816(acc[0][inp * 2 + 0], a0, b[inp][0], b[inp][1]);
                mma16816(acc[1][inp * 2 + 0], a1, b[inp][0], b[inp][1]);
                mma16816(acc[0][inp * 2 + 1], a0, b[inp][2], b[inp][3]);
                mma16816(acc[1][inp * 2 + 1], a1, b[inp][2], b[inp][3]);
            }
        }
    }
}

// ---------------------- merged projection kernel (1-pass, hi-only) ----------
// z=0: q = tau_q * x_h·W_q_hi  (store hi at [n][d])
// z=1: k = tau_k * x_h·W_k_hi  (store hi at [n][d])
// z=2: v = tau_v * W_v_hi·x_h  (store hi transposed at [b][e][m])
__global__ __launch_bounds__(256, 2) void k_proj(const float* __restrict__ tq,
                                                 const float* __restrict__ tk,
                                                 const float* __restrict__ tv)
{
    extern __shared__ char dsm[];
    uint32_t sbase = smem_u32(dsm);
    int z = blockIdx.z;
    size_t woff = (size_t)z * DDIM * DDIM;
    float acc[2][8][4];
    int lane = threadIdx.x & 31, warp = threadIdx.x >> 5;
    int wm = warp & 3, wn = warp >> 2;

    if (z == 2) {
        size_t rowTile = (size_t)blockIdx.x * 128;   // e (8 tiles)
        size_t colTile = (size_t)blockIdx.y * 128;   // flat n (128 tiles)
        const __half* Ap[1] = { g_wth + woff };
        const __half* Bp[1] = { g_xh };
        gemm_mma<1>(Ap, Bp, DDIM, rowTile, colTile, sbase, acc);

        float tau = tv[0];
#pragma unroll
        for (int im = 0; im < 2; im++)
#pragma unroll
            for (int in = 0; in < 8; in++) {
                size_t e0 = rowTile + wm * 32 + im * 16 + (lane >> 2);
                size_t nf = colTile + wn * 64 + in * 8 + (lane & 3) * 2;
                size_t b = nf >> 11, m = nf & (NSEQ - 1);
#pragma unroll
                for (int h = 0; h < 2; h++) {
                    size_t e = e0 + h * 8;
                    __half2 hv;
                    hv.x = __float2half_rn(acc[im][in][2 * h + 0] * tau);
                    hv.y = __float2half_rn(acc[im][in][2 * h + 1] * tau);
                    *(__half2*)&g_vth[(b * DDIM + e) * NSEQ + m] = hv;
                }
            }
    } else {
        size_t rowTile = (size_t)blockIdx.y * 128;   // flat n
        size_t colTile = (size_t)blockIdx.x * 128;   // d
        const __half* Ap[1] = { g_xh };
        const __half* Bp[1] = { g_wth + woff };
        gemm_mma<1>(Ap, Bp, DDIM, rowTile, colTile, sbase, acc);

        float tau = z ? tk[0] : tq[0];
        __half* O = z ? g_kh : g_qh;
#pragma unroll
        for (int im = 0; im < 2; im++)
#pragma unroll
            for (int in = 0; in < 8; in++) {
                size_t n0 = rowTile + wm * 32 + im * 16 + (lane >> 2);
                size_t d  = colTile + wn * 64 + in * 8 + (lane & 3) * 2;
#pragma unroll
                for (int h = 0; h < 2; h++) {
                    size_t n = n0 + h * 8;
                    __half2 hv;
                    hv.x = __float2half_rn(acc[im][in][2 * h + 0] * tau);
                    hv.y = __float2half_rn(acc[im][in][2 * h + 1] * tau);
                    *(__half2*)&O[n * DDIM + d] = hv;
                }
            }
    }
}

// ---------------------- kernel: scores (1-pass) -----------------------------
// C[n][m] = q_h[n]·k_h[m];  S[b][n][m] = C*scale + P[n][m] + c[(n-m)&4095]
__global__ __launch_bounds__(256, 2) void k_scores(const float* __restrict__ P)
{
    extern __shared__ char dsm[];
    uint32_t sbase = smem_u32(dsm);
    int b = blockIdx.z;
    size_t rowTile = (size_t)b * NSEQ + blockIdx.y * 128;   // flat n into q
    size_t colTile = (size_t)b * NSEQ + blockIdx.x * 128;   // flat m into k

    const __half* Ap[1] = { g_qh };
    const __half* Bp[1] = { g_kh };
    float acc[2][8][4];
    gemm_mma<1>(Ap, Bp, DDIM, rowTile, colTile, sbase, acc);

    const float scale = 0.03125f;
    float* S = g_s + (size_t)b * NSEQ * NSEQ;
    int lane = threadIdx.x & 31, warp = threadIdx.x >> 5;
    int wm = warp & 3, wn = warp >> 2;
#pragma unroll
    for (int im = 0; im < 2; im++)
#pragma unroll
        for (int in = 0; in < 8; in++) {
            int n0 = blockIdx.y * 128 + wm * 32 + im * 16 + (lane >> 2);
            int m  = blockIdx.x * 128 + wn * 64 + in * 8 + (lane & 3) * 2;
#pragma unroll
            for (int h = 0; h < 2; h++) {
                int n = n0 + h * 8;
                float2 pv = *(const float2*)&P[(size_t)n * NSEQ + m];
                float2 v;
                v.x = acc[im][in][2 * h + 0] * scale + pv.x + g_c[(n - m) & (TWO_N - 1)];
                v.y = acc[im][in][2 * h + 1] * scale + pv.y + g_c[(n - m - 1) & (TWO_N - 1)];
                *(float2*)&S[(size_t)n * NSEQ + m] = v;
            }
        }
}

// ---------------------- kernel: out = A_h @ v_h (1-pass) --------------------
__global__ __launch_bounds__(256, 2) void k_out(float* __restrict__ O)
{
    extern __shared__ char dsm[];
    uint32_t sbase = smem_u32(dsm);
    int b = blockIdx.z;
    size_t rowTile = (size_t)b * NSEQ + blockIdx.y * 128;   // flat n into attn
    size_t colTile = (size_t)b * DDIM + blockIdx.x * 128;   // flat e into vT

    const __half* Ap[1] = { g_ah };
    const __half* Bp[1] = { g_vth };
    float acc[2][8][4];
    gemm_mma<1>(Ap, Bp, NSEQ, rowTile, colTile, sbase, acc);

    int lane = threadIdx.x & 31, warp = threadIdx.x >> 5;
    int wm = warp & 3, wn = warp >> 2;
#pragma unroll
    for (int im = 0; im < 2; im++)
#pragma unroll
        for (int in = 0; in < 8; in++) {
            int n0 = blockIdx.y * 128 + wm * 32 + im * 16 + (lane >> 2);
            int e  = blockIdx.x * 128 + wn * 64 + in * 8 + (lane & 3) * 2;
#pragma unroll
            for (int h = 0; h < 2; h++) {
                int n = n0 + h * 8;
                float2 v = make_float2(acc[im][in][2 * h + 0], acc[im][in][2 * h + 1]);
                *(float2*)&O[((size_t)b * NSEQ + n) * DDIM + e] = v;
            }
        }
}

// ---------------------- merged prologue kernel ------------------------------
// blocks [0, NBX)            : x -> fp16 convert
// blocks [NBX, NBX+NBW)      : W transpose (hi only)
// blocks [NBX+NBW, +TWO_N)   : circulant bias column
#define NBX ((MTOT*DDIM)/1024)        // 16384
#define NBW (32*32*3)                 // 3072

__global__ __launch_bounds__(256) void k_prologue(
    const float* __restrict__ x,
    const float* __restrict__ Wq, const float* __restrict__ Wk,
    const float* __restrict__ Wv, const float* __restrict__ R)
{
    int blk = blockIdx.x;
    int tid = threadIdx.x;

    if (blk < NBX) {                         // ---- conv_x ----
        size_t i = (size_t)blk * 256 + tid;
        float4 v = ((const float4*)x)[i];
        __half2 h01, h23;
        h01.x = __float2half_rn(v.x); h01.y = __float2half_rn(v.y);
        h23.x = __float2half_rn(v.z); h23.y = __float2half_rn(v.w);
        *(__half2*)&g_xh[i * 4 + 0] = h01;
        *(__half2*)&g_xh[i * 4 + 2] = h23;
    } else if (blk < NBX + NBW) {            // ---- conv_wT ----
        int idx = blk - NBX;
        int z = idx / (32 * 32);
        int rem = idx % (32 * 32);
        const float* W = (z == 0) ? Wq : (z == 1) ? Wk : Wv;
        int bx = (rem % 32) * 32, by = (rem / 32) * 32;
        int tx = tid & 31, ty = tid >> 5;    // 32 x 8
        __shared__ float t[32][33];
#pragma unroll
        for (int i = 0; i < 4; i++)
            t[ty + i * 8][tx] = W[(size_t)(by + ty + i * 8) * DDIM + bx + tx];
        __syncthreads();
        size_t base = (size_t)z * DDIM * DDIM;
#pragma unroll
        for (int i = 0; i < 4; i++) {
            int d = bx + ty + i * 8, k = by + tx;
            g_wth[base + (size_t)d * DDIM + k] = __float2half_rn(t[tx][ty + i * 8]);
        }
    } else {                                 // ---- bias ----
        int t = blk - NBX - NBW;
        int lane = tid & 31, wid = tid >> 5;
        __shared__ float red[8];
        const float w = 6.283185307179586f / (float)TWO_N;
        float s = 0.f;
        for (int j = tid; j < TWO_N; j += 256)
            s += R[j] * cosf(w * (float)((j * t) & (TWO_N - 1)));
#pragma unroll
        for (int o = 16; o; o >>= 1) s += __shfl_xor_sync(0xFFFFFFFFu, s, o);
        if (lane == 0) red[wid] = s;
        __syncthreads();
        if (tid == 0) {
            float tot = 0.f;
#pragma unroll
            for (int i = 0; i < 8; i++) tot += red[i];
            g_c[t] = tot * (1.0f / (float)TWO_N);
        }
    }
}

// ---------------------- softmax (hi-only store) -----------------------------
__global__ __launch_bounds__(256) void softmax_kernel() {
    size_t row = blockIdx.x;
    float* p = g_s + row * NSEQ;
    __half* ah = g_ah + row * NSEQ;
    int t = threadIdx.x, lane = t & 31, wid = t >> 5;
    __shared__ float red[8];

    float x[8];
#pragma unroll
    for (int i = 0; i < 8; i++) x[i] = p[t + i * 256];
    float m = x[0];
#pragma unroll
    for (int i = 1; i < 8; i++) m = fmaxf(m, x[i]);
#pragma unroll
    for (int o = 16; o; o >>= 1) m = fmaxf(m, __shfl_xor_sync(0xFFFFFFFFu, m, o));
    if (lane == 0) red[wid] = m;
    __syncthreads();
    float bm = red[0];
#pragma unroll
    for (int i = 1; i < 8; i++) bm = fmaxf(bm, red[i]);
    __syncthreads();
    float s = 0.f;
#pragma unroll
    for (int i = 0; i < 8; i++) { x[i] = expf(x[i] - bm); s += x[i]; }
#pragma unroll
    for (int o = 16; o; o >>= 1) s += __shfl_xor_sync(0xFFFFFFFFu, s, o);
    if (lane == 0) red[wid] = s;
    __syncthreads();
    float tot = red[0];
#pragma unroll
    for (int i = 1; i < 8; i++) tot += red[i];
    float inv = 1.0f / tot;
#pragma unroll
    for (int i = 0; i < 8; i++)
        ah[t + i * 256] = __float2half_rn(x[i] * inv);
}

// ---------------------- launch ----------------------------------------------
extern "C" void kernel_launch(void* const* d_in, const int* in_sizes, int n_in,
                              void* d_out, int out_size)
{
    const float* x  = (const float*)d_in[0];
    const float* Wq = (const float*)d_in[1];
    const float* Wk = (const float*)d_in[2];
    const float* Wv = (const float*)d_in[3];
    const float* P  = (const float*)d_in[4];
    const float* R  = (const float*)d_in[5];
    const float* tq = (const float*)d_in[6];
    const float* tk = (const float*)d_in[7];
    const float* tv = (const float*)d_in[8];
    float* out = (float*)d_out;

    cudaFuncSetAttribute(k_proj,   cudaFuncAttributeMaxDynamicSharedMemorySize, SMEMB);
    cudaFuncSetAttribute(k_scores, cudaFuncAttributeMaxDynamicSharedMemorySize, SMEMB);
    cudaFuncSetAttribute(k_out,    cudaFuncAttributeMaxDynamicSharedMemorySize, SMEMB);

    k_prologue<<<NBX + NBW + TWO_N, 256>>>(x, Wq, Wk, Wv, R);
    k_proj  <<<dim3(DDIM / 128, MTOT / 128, 3), 256, SMEMB>>>(tq, tk, tv);
    k_scores<<<dim3(NSEQ / 128, NSEQ / 128, BATCH), 256, SMEMB>>>(P);
    softmax_kernel<<<dim3(BATCH * NSEQ), 256>>>();
    k_out   <<<dim3(DDIM / 128, NSEQ / 128, BATCH), 256, SMEMB>>>(out);
}